// round 10
// baseline (speedup 1.0000x reference)
#include <cuda_runtime.h>
#include <cuda_bf16.h>
#include <math.h>
#include <stdint.h>

#define BB   4
#define LL   1024
#define BL   4096
#define DD   768
#define HH   12
#define DKH  64
#define FF   3072
#define MDIST 100
#define TBL  201
#define QN   2304   // combined QKV width

typedef __nv_bfloat16 bf16;

// ---------------- scratch ----------------
__device__ float g_pre[BL * DD];
__device__ float g_t1[BL * DD];
__device__ float g_bqkv[QN];

__device__ __align__(16) bf16 g_tokh[BL * DD],  g_tokl[BL * DD];
__device__ __align__(16) bf16 g_qkvh[(size_t)BL * QN], g_qkvl[(size_t)BL * QN];
__device__ __align__(16) bf16 g_ctxh[BL * DD],  g_ctxl[BL * DD];
__device__ __align__(16) bf16 g_t1h[BL * DD],   g_t1l[BL * DD];
__device__ __align__(16) bf16 g_ffh[(size_t)BL * FF], g_ffl[(size_t)BL * FF];

__device__ __align__(16) bf16 g_wqkvh[(size_t)QN * DD], g_wqkvl[(size_t)QN * DD];
__device__ __align__(16) bf16 g_woh[DD * DD], g_wol[DD * DD];
__device__ __align__(16) bf16 g_w1h[(size_t)DD * FF], g_w1l[(size_t)DD * FF];
__device__ __align__(16) bf16 g_w2h[(size_t)DD * FF], g_w2l[(size_t)DD * FF];

// =================== helpers ===================
__device__ __forceinline__ uint32_t smem_u32(const void* p) {
    uint32_t a;
    asm("{ .reg .u64 t; cvta.to.shared.u64 t, %1; cvt.u32.u64 %0, t; }" : "=r"(a) : "l"(p));
    return a;
}
__device__ __forceinline__ void ldsm4(uint32_t* r, uint32_t addr) {
    asm volatile("ldmatrix.sync.aligned.m8n8.x4.shared.b16 {%0,%1,%2,%3}, [%4];"
        : "=r"(r[0]), "=r"(r[1]), "=r"(r[2]), "=r"(r[3]) : "r"(addr));
}
__device__ __forceinline__ void ldsm4t(uint32_t* r, uint32_t addr) {
    asm volatile("ldmatrix.sync.aligned.m8n8.x4.trans.shared.b16 {%0,%1,%2,%3}, [%4];"
        : "=r"(r[0]), "=r"(r[1]), "=r"(r[2]), "=r"(r[3]) : "r"(addr));
}
__device__ __forceinline__ void mma16816(float* d, const uint32_t* a, const uint32_t* b) {
    asm volatile("mma.sync.aligned.m16n8k16.row.col.f32.bf16.bf16.f32 "
        "{%0,%1,%2,%3}, {%4,%5,%6,%7}, {%8,%9}, {%0,%1,%2,%3};"
        : "+f"(d[0]), "+f"(d[1]), "+f"(d[2]), "+f"(d[3])
        : "r"(a[0]), "r"(a[1]), "r"(a[2]), "r"(a[3]), "r"(b[0]), "r"(b[1]));
}
__device__ __forceinline__ void split2(float a, float b, uint32_t& hi, uint32_t& lo) {
    bf16 ha = __float2bfloat16(a), hb = __float2bfloat16(b);
    bf16 la = __float2bfloat16(a - __bfloat162float(ha));
    bf16 lb = __float2bfloat16(b - __bfloat162float(hb));
    __nv_bfloat162 th, tl;
    th.x = ha; th.y = hb; tl.x = la; tl.y = lb;
    hi = *(uint32_t*)&th; lo = *(uint32_t*)&tl;
}

// =================== conversions ===================
__global__ void __launch_bounds__(256)
cvt_split(const float* __restrict__ X, bf16* __restrict__ H, bf16* __restrict__ L, int n4)
{
    int i = blockIdx.x * 256 + threadIdx.x;
    if (i >= n4) return;
    float4 v = ((const float4*)X)[i];
    uint32_t h0, l0, h1, l1;
    split2(v.x, v.y, h0, l0);
    split2(v.z, v.w, h1, l1);
    uint2 hh = {h0, h1}, ll = {l0, l1};
    ((uint2*)H)[i] = hh;
    ((uint2*)L)[i] = ll;
}

__global__ void __launch_bounds__(256)
cvt_wT(const float* __restrict__ W, bf16* __restrict__ TH, bf16* __restrict__ TL, int K, int N)
{
    __shared__ float t[32][33];
    const int n0 = blockIdx.x * 32, k0 = blockIdx.y * 32;
    const int tx = threadIdx.x & 31, ty = threadIdx.x >> 5;
    #pragma unroll
    for (int i = 0; i < 4; ++i)
        t[ty + 8 * i][tx] = W[(size_t)(k0 + ty + 8 * i) * N + n0 + tx];
    __syncthreads();
    #pragma unroll
    for (int i = 0; i < 4; ++i) {
        float x = t[tx][ty + 8 * i];
        bf16 h = __float2bfloat16(x);
        size_t o = (size_t)(n0 + ty + 8 * i) * K + k0 + tx;
        TH[o] = h;
        TL[o] = __float2bfloat16(x - __bfloat162float(h));
    }
}

__global__ void concat3(const float* a, const float* b, const float* c, float* o)
{
    int i = threadIdx.x + blockIdx.x * 256;
    if (i < DD) { o[i] = a[i]; o[DD + i] = b[i]; o[2 * DD + i] = c[i]; }
}

// =================== mma.sync bf16-split GEMM ===================
// EPI: 2 = +bias,+residual (fp32) ; 3 = +bias -> bf16 h/l ; 4 = +bias,relu -> bf16 h/l
#define AST 40

template<int EPI>
__global__ void __launch_bounds__(256)
gemm_mma(const bf16* __restrict__ Ah, const bf16* __restrict__ Al,
         const bf16* __restrict__ Bh, const bf16* __restrict__ Bl,
         const float* __restrict__ bias, const float* __restrict__ res,
         float* __restrict__ C, bf16* __restrict__ Ch, bf16* __restrict__ Cl,
         int K, int N)
{
    __shared__ bf16 sAh[128 * AST];
    __shared__ bf16 sAl[128 * AST];
    __shared__ bf16 sBh[128 * AST];
    __shared__ bf16 sBl[128 * AST];

    const int tid = threadIdx.x, wid = tid >> 5, lane = tid & 31;
    const int m0 = blockIdx.y * 128, n0 = blockIdx.x * 128;
    const int wm = (wid >> 2) * 64;
    const int wn = (wid & 3) * 32;

    float acc[4][4][4] = {};

    uint4 pah[2], pal[2], pbh[2], pbl[2];

    const bf16* Ahp = Ah + (size_t)m0 * K;
    const bf16* Alp = Al + (size_t)m0 * K;
    const bf16* Bhp = Bh + (size_t)n0 * K;
    const bf16* Blp = Bl + (size_t)n0 * K;

    auto fetch = [&](int k0) {
        #pragma unroll
        for (int it = 0; it < 2; ++it) {
            int idx = tid + it * 256;
            int row = idx >> 2, g = idx & 3;
            size_t go = (size_t)row * K + k0 + g * 8;
            pah[it] = *(const uint4*)(Ahp + go);
            pal[it] = *(const uint4*)(Alp + go);
            pbh[it] = *(const uint4*)(Bhp + go);
            pbl[it] = *(const uint4*)(Blp + go);
        }
    };
    auto stage = [&]() {
        #pragma unroll
        for (int it = 0; it < 2; ++it) {
            int idx = tid + it * 256;
            int row = idx >> 2, g = idx & 3;
            *(uint4*)&sAh[row * AST + g * 8] = pah[it];
            *(uint4*)&sAl[row * AST + g * 8] = pal[it];
            *(uint4*)&sBh[row * AST + g * 8] = pbh[it];
            *(uint4*)&sBl[row * AST + g * 8] = pbl[it];
        }
    };

    const int a_row = wm + (lane & 15);
    const int a_kof = (lane >> 4) << 3;
    const int b_row = wn + ((lane >> 4) << 3) + (lane & 7);
    const int b_kof = ((lane >> 3) & 1) << 3;

    const uint32_t sAh_b = smem_u32(sAh), sAl_b = smem_u32(sAl);
    const uint32_t sBh_b = smem_u32(sBh), sBl_b = smem_u32(sBl);

    fetch(0);
    stage();
    __syncthreads();

    const int ns = K >> 5;
    for (int s = 0; s < ns; ++s) {
        if (s + 1 < ns) fetch((s + 1) << 5);

        #pragma unroll
        for (int kstep = 0; kstep < 2; ++kstep) {
            const int kk = kstep * 16;
            uint32_t afh[4][4], afl[4][4];
            #pragma unroll
            for (int mi = 0; mi < 4; ++mi) {
                uint32_t off = (uint32_t)((a_row + mi * 16) * AST + kk + a_kof) * 2;
                ldsm4(afh[mi], sAh_b + off);
                ldsm4(afl[mi], sAl_b + off);
            }
            uint32_t bfh[2][4], bfl[2][4];
            #pragma unroll
            for (int g = 0; g < 2; ++g) {
                uint32_t off = (uint32_t)((b_row + g * 16) * AST + kk + b_kof) * 2;
                ldsm4(bfh[g], sBh_b + off);
                ldsm4(bfl[g], sBl_b + off);
            }
            #pragma unroll
            for (int mi = 0; mi < 4; ++mi)
                #pragma unroll
                for (int ni = 0; ni < 4; ++ni) {
                    const uint32_t* bh_ = &bfh[ni >> 1][(ni & 1) * 2];
                    const uint32_t* bl_ = &bfl[ni >> 1][(ni & 1) * 2];
                    mma16816(acc[mi][ni], afh[mi], bh_);
                    mma16816(acc[mi][ni], afh[mi], bl_);
                    mma16816(acc[mi][ni], afl[mi], bh_);
                }
        }

        __syncthreads();
        if (s + 1 < ns) {
            stage();
            __syncthreads();
        }
    }

    const int er = lane >> 2, ec = (lane & 3) * 2;
    #pragma unroll
    for (int mi = 0; mi < 4; ++mi) {
        #pragma unroll
        for (int hrow = 0; hrow < 2; ++hrow) {
            int row = m0 + wm + mi * 16 + er + hrow * 8;
            #pragma unroll
            for (int ni = 0; ni < 4; ++ni) {
                int col = n0 + wn + ni * 8 + ec;
                float v0 = acc[mi][ni][hrow * 2 + 0] + bias[col];
                float v1 = acc[mi][ni][hrow * 2 + 1] + bias[col + 1];
                if (EPI == 4) { v0 = fmaxf(v0, 0.0f); v1 = fmaxf(v1, 0.0f); }
                if (EPI == 2) {
                    v0 += res[(size_t)row * N + col];
                    v1 += res[(size_t)row * N + col + 1];
                    float2 o = {v0, v1};
                    *(float2*)(C + (size_t)row * N + col) = o;
                } else {
                    uint32_t hi, lo;
                    split2(v0, v1, hi, lo);
                    *(uint32_t*)(Ch + (size_t)row * N + col) = hi;
                    *(uint32_t*)(Cl + (size_t)row * N + col) = lo;
                }
            }
        }
    }
}

// =================== fused flash attention (q-tile 64, 128 thr) ===============
#define FST 72

__global__ void __launch_bounds__(128)
flash_kernel(const bf16* __restrict__ qkvh, const bf16* __restrict__ qkvl,
             const float* __restrict__ pos, const float* __restrict__ pmask,
             const float* __restrict__ amask, const unsigned char* __restrict__ pad,
             const float* __restrict__ table,
             bf16* __restrict__ ctxh, bf16* __restrict__ ctxl)
{
    __shared__ bf16 sKh[64 * FST], sKl[64 * FST];
    __shared__ bf16 sVh[64 * FST], sVl[64 * FST];
    __shared__ float pxq[64], pyq[64], pmq[64];
    __shared__ float pxk[64], pyk[64], pmk[64], padk[64];

    const int q0 = blockIdx.x * 64;
    const int bh = blockIdx.y;
    const int b = bh / HH, h = bh % HH;
    const int tid = threadIdx.x, wid = tid >> 5, lane = tid & 31;
    const float* tbl = table + (size_t)h * TBL * TBL;

    const bf16* Qh = qkvh + (size_t)(b * LL) * QN + h * DKH;
    const bf16* Ql = qkvl + (size_t)(b * LL) * QN + h * DKH;
    const bf16* Kh = Qh + DD;
    const bf16* Kl = Ql + DD;
    const bf16* Vh = Qh + 2 * DD;
    const bf16* Vl = Ql + 2 * DD;

    if (tid < 64) {
        int l = b * LL + q0 + tid;
        pxq[tid] = pos[2 * (size_t)l];
        pyq[tid] = pos[2 * (size_t)l + 1];
        pmq[tid] = pmask[l];
    }

    // stage Q (reuse K buffers) and load Q fragments to registers
    #pragma unroll
    for (int it = 0; it < 4; ++it) {
        int idx = tid + it * 128;
        int row = idx >> 3, g = idx & 7;
        size_t go = (size_t)(q0 + row) * QN + g * 8;
        *(uint4*)&sKh[row * FST + g * 8] = *(const uint4*)(Qh + go);
        *(uint4*)&sKl[row * FST + g * 8] = *(const uint4*)(Ql + go);
    }
    __syncthreads();

    const uint32_t sKh_b = smem_u32(sKh), sKl_b = smem_u32(sKl);
    const uint32_t sVh_b = smem_u32(sVh), sVl_b = smem_u32(sVl);

    uint32_t qfh[4][4], qfl[4][4];
    {
        int a_row = wid * 16 + (lane & 15);
        int a_kof = (lane >> 4) << 3;
        #pragma unroll
        for (int j = 0; j < 4; ++j) {
            uint32_t off = (uint32_t)(a_row * FST + j * 16 + a_kof) * 2;
            ldsm4(qfh[j], sKh_b + off);
            ldsm4(qfl[j], sKl_b + off);
        }
    }
    __syncthreads();

    const int er = lane >> 2, ec = (lane & 3) * 2;
    const int qr0 = q0 + wid * 16 + er;
    float mrow[2] = {-1e30f, -1e30f}, lrow[2] = {0.f, 0.f};
    float accO[8][4] = {};

    for (int kt = 0; kt < 16; ++kt) {
        const int k0 = kt * 64;
        #pragma unroll
        for (int it = 0; it < 4; ++it) {
            int idx = tid + it * 128;
            int row = idx >> 3, g = idx & 7;
            size_t go = (size_t)(k0 + row) * QN + g * 8;
            *(uint4*)&sKh[row * FST + g * 8] = *(const uint4*)(Kh + go);
            *(uint4*)&sKl[row * FST + g * 8] = *(const uint4*)(Kl + go);
            *(uint4*)&sVh[row * FST + g * 8] = *(const uint4*)(Vh + go);
            *(uint4*)&sVl[row * FST + g * 8] = *(const uint4*)(Vl + go);
        }
        if (tid < 64) {
            int l = b * LL + k0 + tid;
            pxk[tid] = pos[2 * (size_t)l];
            pyk[tid] = pos[2 * (size_t)l + 1];
            pmk[tid] = pmask[l];
            padk[tid] = pad[l] ? 1.f : 0.f;
        }
        __syncthreads();

        // ---- S = Q K^T (3-term split) ----
        float accS[8][4] = {};
        #pragma unroll
        for (int j = 0; j < 4; ++j) {
            #pragma unroll
            for (int g = 0; g < 4; ++g) {
                uint32_t kh[4], kl[4];
                int b_row = g * 16 + ((lane >> 4) << 3) + (lane & 7);
                uint32_t off = (uint32_t)(b_row * FST + j * 16 + (((lane >> 3) & 1) << 3)) * 2;
                ldsm4(kh, sKh_b + off);
                ldsm4(kl, sKl_b + off);
                mma16816(accS[2 * g],     qfh[j], kh);
                mma16816(accS[2 * g],     qfh[j], kl);
                mma16816(accS[2 * g],     qfl[j], kh);
                mma16816(accS[2 * g + 1], qfh[j], kh + 2);
                mma16816(accS[2 * g + 1], qfh[j], kl + 2);
                mma16816(accS[2 * g + 1], qfl[j], kh + 2);
            }
        }

        // ---- bias + mask + online softmax ----
        float pxr[2] = {pxq[wid * 16 + er], pxq[wid * 16 + er + 8]};
        float pyr[2] = {pyq[wid * 16 + er], pyq[wid * 16 + er + 8]};
        float pmr[2] = {pmq[wid * 16 + er], pmq[wid * 16 + er + 8]};
        float newm[2] = {mrow[0], mrow[1]};
        #pragma unroll
        for (int ni = 0; ni < 8; ++ni) {
            #pragma unroll
            for (int r = 0; r < 2; ++r) {
                int kj0 = ni * 8 + ec;
                float2 am = *(const float2*)(amask + (size_t)(b * LL + qr0 + 8 * r) * LL + k0 + kj0);
                #pragma unroll
                for (int u = 0; u < 2; ++u) {
                    int kj = kj0 + u;
                    float s = accS[ni][2 * r + u] * 0.125f;
                    float ddx = fminf(fmaxf(rintf(pxr[r] - pxk[kj]), -(float)MDIST), (float)MDIST);
                    float ddy = fminf(fmaxf(rintf(pyr[r] - pyk[kj]), -(float)MDIST), (float)MDIST);
                    int dx = (int)ddx + MDIST, dy = (int)ddy + MDIST;
                    s += tbl[dy * TBL + dx] * (pmr[r] * pmk[kj]);
                    float amv = (u == 0) ? am.x : am.y;
                    if (amv == 0.f || padk[kj] != 0.f) s = -1e9f;
                    accS[ni][2 * r + u] = s;
                    newm[r] = fmaxf(newm[r], s);
                }
            }
        }
        #pragma unroll
        for (int r = 0; r < 2; ++r) {
            newm[r] = fmaxf(newm[r], __shfl_xor_sync(0xffffffffu, newm[r], 1));
            newm[r] = fmaxf(newm[r], __shfl_xor_sync(0xffffffffu, newm[r], 2));
        }
        float alpha[2], psum[2] = {0.f, 0.f};
        #pragma unroll
        for (int r = 0; r < 2; ++r) {
            alpha[r] = __expf(mrow[r] - newm[r]);
            mrow[r] = newm[r];
        }
        #pragma unroll
        for (int ni = 0; ni < 8; ++ni)
            #pragma unroll
            for (int u = 0; u < 4; ++u) {
                float p = __expf(accS[ni][u] - newm[u >> 1]);
                accS[ni][u] = p;
                psum[u >> 1] += p;
            }
        #pragma unroll
        for (int r = 0; r < 2; ++r) {
            psum[r] += __shfl_xor_sync(0xffffffffu, psum[r], 1);
            psum[r] += __shfl_xor_sync(0xffffffffu, psum[r], 2);
            lrow[r] = lrow[r] * alpha[r] + psum[r];
        }
        #pragma unroll
        for (int ni = 0; ni < 8; ++ni)
            #pragma unroll
            for (int u = 0; u < 4; ++u)
                accO[ni][u] *= alpha[u >> 1];

        // ---- O += P V (3-term split), P frags built in registers ----
        #pragma unroll
        for (int j = 0; j < 4; ++j) {
            uint32_t afh[4], afl[4];
            split2(accS[2 * j][0],     accS[2 * j][1],     afh[0], afl[0]);
            split2(accS[2 * j][2],     accS[2 * j][3],     afh[1], afl[1]);
            split2(accS[2 * j + 1][0], accS[2 * j + 1][1], afh[2], afl[2]);
            split2(accS[2 * j + 1][2], accS[2 * j + 1][3], afh[3], afl[3]);
            #pragma unroll
            for (int g = 0; g < 4; ++g) {
                uint32_t vh[4], vl[4];
                uint32_t off = (uint32_t)((j * 16 + (lane & 15)) * FST + g * 16 + ((lane >> 4) << 3)) * 2;
                ldsm4t(vh, sVh_b + off);
                ldsm4t(vl, sVl_b + off);
                mma16816(accO[2 * g],     afh, vh);
                mma16816(accO[2 * g],     afh, vl);
                mma16816(accO[2 * g],     afl, vh);
                mma16816(accO[2 * g + 1], afh, vh + 2);
                mma16816(accO[2 * g + 1], afh, vl + 2);
                mma16816(accO[2 * g + 1], afl, vh + 2);
            }
        }
        __syncthreads();
    }

    // ---- write ctx (bf16 split) ----
    #pragma unroll
    for (int r = 0; r < 2; ++r) {
        float inv = 1.f / lrow[r];
        #pragma unroll
        for (int ni = 0; ni < 8; ++ni) {
            uint32_t hi, lo;
            split2(accO[ni][2 * r] * inv, accO[ni][2 * r + 1] * inv, hi, lo);
            size_t o = (size_t)(b * LL + qr0 + 8 * r) * DD + h * DKH + ni * 8 + ec;
            *(uint32_t*)(ctxh + o) = hi;
            *(uint32_t*)(ctxl + o) = lo;
        }
    }
}

// ------------- LayerNorm (SPLIT: also emit bf16 h/l) -------------------------
template<bool SPLIT>
__global__ void __launch_bounds__(256)
ln_kernel(const float* __restrict__ X, const float* __restrict__ g,
          const float* __restrict__ bt, float* __restrict__ O,
          bf16* __restrict__ Oh, bf16* __restrict__ Ol)
{
    const int row = blockIdx.x;
    const float* x = X + (size_t)row * DD;
    const int tid = threadIdx.x;

    float v[3];
    #pragma unroll
    for (int i = 0; i < 3; ++i) v[i] = x[tid + i * 256];

    __shared__ float red[256];
    float s = v[0] + v[1] + v[2];
    red[tid] = s; __syncthreads();
    for (int st = 128; st > 0; st >>= 1) {
        if (tid < st) red[tid] += red[tid + st];
        __syncthreads();
    }
    float mean = red[0] * (1.0f / DD);
    __syncthreads();

    float d0 = v[0] - mean, d1 = v[1] - mean, d2 = v[2] - mean;
    red[tid] = d0 * d0 + d1 * d1 + d2 * d2; __syncthreads();
    for (int st = 128; st > 0; st >>= 1) {
        if (tid < st) red[tid] += red[tid + st];
        __syncthreads();
    }
    float var = red[0] * (1.0f / DD);
    float inv = rsqrtf(var + 1e-5f);

    #pragma unroll
    for (int i = 0; i < 3; ++i) {
        int c = tid + i * 256;
        float o = (v[i] - mean) * inv * g[c] + bt[c];
        O[(size_t)row * DD + c] = o;
        if (SPLIT) {
            bf16 h = __float2bfloat16(o);
            Oh[(size_t)row * DD + c] = h;
            Ol[(size_t)row * DD + c] = __float2bfloat16(o - __bfloat162float(h));
        }
    }
}

// ------------------------------- launch ---------------------------------------
extern "C" void kernel_launch(void* const* d_in, const int* in_sizes, int n_in,
                              void* d_out, int out_size)
{
    const float* tokens = (const float*)d_in[0];
    const float* pos    = (const float*)d_in[1];
    const float* pmask  = (const float*)d_in[2];
    const float* amask  = (const float*)d_in[3];
    const unsigned char* pad = (const unsigned char*)d_in[4];
    const float* Wq = (const float*)d_in[5];
    const float* bq = (const float*)d_in[6];
    const float* Wk = (const float*)d_in[7];
    const float* bk = (const float*)d_in[8];
    const float* Wv = (const float*)d_in[9];
    const float* bv = (const float*)d_in[10];
    const float* Wo = (const float*)d_in[11];
    const float* bo = (const float*)d_in[12];
    const float* table = (const float*)d_in[13];
    const float* W1 = (const float*)d_in[14];
    const float* b1 = (const float*)d_in[15];
    const float* W2 = (const float*)d_in[16];
    const float* b2 = (const float*)d_in[17];
    const float* ln1g = (const float*)d_in[18];
    const float* ln1b = (const float*)d_in[19];
    const float* ln2g = (const float*)d_in[20];
    const float* ln2b = (const float*)d_in[21];
    float* out = (float*)d_out;

    float *Pb, *Tb, *bqkv;
    cudaGetSymbolAddress((void**)&Pb, g_pre);
    cudaGetSymbolAddress((void**)&Tb, g_t1);
    cudaGetSymbolAddress((void**)&bqkv, g_bqkv);

    bf16 *tokh, *tokl, *qkvh, *qkvl, *ctxh, *ctxl, *t1h, *t1l, *ffh, *ffl;
    cudaGetSymbolAddress((void**)&tokh, g_tokh); cudaGetSymbolAddress((void**)&tokl, g_tokl);
    cudaGetSymbolAddress((void**)&qkvh, g_qkvh); cudaGetSymbolAddress((void**)&qkvl, g_qkvl);
    cudaGetSymbolAddress((void**)&ctxh, g_ctxh); cudaGetSymbolAddress((void**)&ctxl, g_ctxl);
    cudaGetSymbolAddress((void**)&t1h, g_t1h);   cudaGetSymbolAddress((void**)&t1l, g_t1l);
    cudaGetSymbolAddress((void**)&ffh, g_ffh);   cudaGetSymbolAddress((void**)&ffl, g_ffl);

    bf16 *wqkvh, *wqkvl, *woh, *wol, *w1h, *w1l, *w2h, *w2l;
    cudaGetSymbolAddress((void**)&wqkvh, g_wqkvh); cudaGetSymbolAddress((void**)&wqkvl, g_wqkvl);
    cudaGetSymbolAddress((void**)&woh, g_woh); cudaGetSymbolAddress((void**)&wol, g_wol);
    cudaGetSymbolAddress((void**)&w1h, g_w1h); cudaGetSymbolAddress((void**)&w1l, g_w1l);
    cudaGetSymbolAddress((void**)&w2h, g_w2h); cudaGetSymbolAddress((void**)&w2l, g_w2l);

    // weight transpose + split (combined QKV)
    dim3 gw(DD / 32, DD / 32);
    cvt_wT<<<gw, 256>>>(Wq, wqkvh,                       wqkvl,                       DD, DD);
    cvt_wT<<<gw, 256>>>(Wk, wqkvh + (size_t)DD * DD,     wqkvl + (size_t)DD * DD,     DD, DD);
    cvt_wT<<<gw, 256>>>(Wv, wqkvh + (size_t)2 * DD * DD, wqkvl + (size_t)2 * DD * DD, DD, DD);
    cvt_wT<<<gw, 256>>>(Wo, woh, wol, DD, DD);
    cvt_wT<<<dim3(FF / 32, DD / 32), 256>>>(W1, w1h, w1l, DD, FF);
    cvt_wT<<<dim3(DD / 32, FF / 32), 256>>>(W2, w2h, w2l, FF, DD);
    concat3<<<3, 256>>>(bq, bk, bv, bqkv);

    // tokens split (A for QKV, once)
    cvt_split<<<(BL * DD / 4 + 255) / 256, 256>>>(tokens, tokh, tokl, BL * DD / 4);

    // fused QKV GEMM  -> bf16 split [BL, 2304]
    gemm_mma<3><<<dim3(QN / 128, BL / 128), 256>>>(tokh, tokl, wqkvh, wqkvl, bqkv,
                                                   nullptr, nullptr, qkvh, qkvl, DD, QN);

    // fused attention -> ctx bf16 split
    dim3 gfa(LL / 64, BB * HH);
    flash_kernel<<<gfa, 128>>>(qkvh, qkvl, pos, pmask, amask, pad, table, ctxh, ctxl);

    // out proj + residual -> fp32, LN1 (emits fp32 + bf16 split)
    gemm_mma<2><<<dim3(DD / 128, BL / 128), 256>>>(ctxh, ctxl, woh, wol, bo,
                                                   tokens, Pb, nullptr, nullptr, DD, DD);
    ln_kernel<true><<<BL, 256>>>(Pb, ln1g, ln1b, Tb, t1h, t1l);

    // FFN
    gemm_mma<4><<<dim3(FF / 128, BL / 128), 256>>>(t1h, t1l, w1h, w1l, b1,
                                                   nullptr, nullptr, ffh, ffl, DD, FF);
    gemm_mma<2><<<dim3(DD / 128, BL / 128), 256>>>(ffh, ffl, w2h, w2l, b2,
                                                   Tb, Pb, nullptr, nullptr, FF, DD);
    ln_kernel<false><<<BL, 256>>>(Pb, ln2g, ln2b, out, nullptr, nullptr);
}

// round 11
// speedup vs baseline: 1.0088x; 1.0088x over previous
#include <cuda_runtime.h>
#include <cuda_bf16.h>
#include <math.h>
#include <stdint.h>

#define BB   4
#define LL   1024
#define BL   4096
#define DD   768
#define HH   12
#define DKH  64
#define FF   3072
#define MDIST 100
#define TBL  201
#define QN   2304   // combined QKV width

typedef __nv_bfloat16 bf16;

// ---------------- scratch ----------------
__device__ float g_pre[BL * DD];
__device__ float g_t1[BL * DD];
__device__ float g_bqkv[QN];

__device__ __align__(16) bf16 g_tokh[BL * DD],  g_tokl[BL * DD];
__device__ __align__(16) bf16 g_qkvh[(size_t)BL * QN], g_qkvl[(size_t)BL * QN];
__device__ __align__(16) bf16 g_ctxh[BL * DD],  g_ctxl[BL * DD];
__device__ __align__(16) bf16 g_t1h[BL * DD],   g_t1l[BL * DD];
__device__ __align__(16) bf16 g_ffh[(size_t)BL * FF], g_ffl[(size_t)BL * FF];

__device__ __align__(16) bf16 g_wqkvh[(size_t)QN * DD], g_wqkvl[(size_t)QN * DD];
__device__ __align__(16) bf16 g_woh[DD * DD], g_wol[DD * DD];
__device__ __align__(16) bf16 g_w1h[(size_t)DD * FF], g_w1l[(size_t)DD * FF];
__device__ __align__(16) bf16 g_w2h[(size_t)DD * FF], g_w2l[(size_t)DD * FF];

// =================== helpers ===================
__device__ __forceinline__ uint32_t smem_u32(const void* p) {
    uint32_t a;
    asm("{ .reg .u64 t; cvta.to.shared.u64 t, %1; cvt.u32.u64 %0, t; }" : "=r"(a) : "l"(p));
    return a;
}
__device__ __forceinline__ void ldsm4(uint32_t* r, uint32_t addr) {
    asm volatile("ldmatrix.sync.aligned.m8n8.x4.shared.b16 {%0,%1,%2,%3}, [%4];"
        : "=r"(r[0]), "=r"(r[1]), "=r"(r[2]), "=r"(r[3]) : "r"(addr));
}
__device__ __forceinline__ void ldsm4t(uint32_t* r, uint32_t addr) {
    asm volatile("ldmatrix.sync.aligned.m8n8.x4.trans.shared.b16 {%0,%1,%2,%3}, [%4];"
        : "=r"(r[0]), "=r"(r[1]), "=r"(r[2]), "=r"(r[3]) : "r"(addr));
}
__device__ __forceinline__ void mma16816(float* d, const uint32_t* a, const uint32_t* b) {
    asm volatile("mma.sync.aligned.m16n8k16.row.col.f32.bf16.bf16.f32 "
        "{%0,%1,%2,%3}, {%4,%5,%6,%7}, {%8,%9}, {%0,%1,%2,%3};"
        : "+f"(d[0]), "+f"(d[1]), "+f"(d[2]), "+f"(d[3])
        : "r"(a[0]), "r"(a[1]), "r"(a[2]), "r"(a[3]), "r"(b[0]), "r"(b[1]));
}
__device__ __forceinline__ void split2(float a, float b, uint32_t& hi, uint32_t& lo) {
    bf16 ha = __float2bfloat16(a), hb = __float2bfloat16(b);
    bf16 la = __float2bfloat16(a - __bfloat162float(ha));
    bf16 lb = __float2bfloat16(b - __bfloat162float(hb));
    __nv_bfloat162 th, tl;
    th.x = ha; th.y = hb; tl.x = la; tl.y = lb;
    hi = *(uint32_t*)&th; lo = *(uint32_t*)&tl;
}

// =================== conversions ===================
// tokens split + bias concat folded into one launch (extra trailing blocks do bias)
__global__ void __launch_bounds__(256)
cvt_split_bias(const float* __restrict__ X, bf16* __restrict__ H, bf16* __restrict__ L,
               int n4, const float* __restrict__ bq, const float* __restrict__ bk,
               const float* __restrict__ bv, float* __restrict__ bqkv)
{
    int i = blockIdx.x * 256 + threadIdx.x;
    if (i < n4) {
        float4 v = ((const float4*)X)[i];
        uint32_t h0, l0, h1, l1;
        split2(v.x, v.y, h0, l0);
        split2(v.z, v.w, h1, l1);
        uint2 hh = {h0, h1}, ll = {l0, l1};
        ((uint2*)H)[i] = hh;
        ((uint2*)L)[i] = ll;
        return;
    }
    int j = i - n4;                  // 0 .. 2303 handled by trailing blocks
    if (j < DD)           bqkv[j] = bq[j];
    else if (j < 2 * DD)  bqkv[j] = bk[j - DD];
    else if (j < 3 * DD)  bqkv[j] = bv[j - 2 * DD];
}

// 4 D×D weight transposes in one launch: z = 0..2 -> QKV slices, z = 3 -> Wo
__global__ void __launch_bounds__(256)
cvt_wT4(const float* __restrict__ Wq, const float* __restrict__ Wk,
        const float* __restrict__ Wv, const float* __restrict__ Wo,
        bf16* __restrict__ qkvTH, bf16* __restrict__ qkvTL,
        bf16* __restrict__ oTH, bf16* __restrict__ oTL)
{
    __shared__ float t[32][33];
    const int z = blockIdx.z;
    const float* W = (z == 0) ? Wq : (z == 1) ? Wk : (z == 2) ? Wv : Wo;
    bf16* TH = (z < 3) ? (qkvTH + (size_t)z * DD * DD) : oTH;
    bf16* TL = (z < 3) ? (qkvTL + (size_t)z * DD * DD) : oTL;

    const int n0 = blockIdx.x * 32, k0 = blockIdx.y * 32;
    const int tx = threadIdx.x & 31, ty = threadIdx.x >> 5;
    #pragma unroll
    for (int i = 0; i < 4; ++i)
        t[ty + 8 * i][tx] = W[(size_t)(k0 + ty + 8 * i) * DD + n0 + tx];
    __syncthreads();
    #pragma unroll
    for (int i = 0; i < 4; ++i) {
        float x = t[tx][ty + 8 * i];
        bf16 h = __float2bfloat16(x);
        size_t o = (size_t)(n0 + ty + 8 * i) * DD + k0 + tx;
        TH[o] = h;
        TL[o] = __float2bfloat16(x - __bfloat162float(h));
    }
}

__global__ void __launch_bounds__(256)
cvt_wT(const float* __restrict__ W, bf16* __restrict__ TH, bf16* __restrict__ TL, int K, int N)
{
    __shared__ float t[32][33];
    const int n0 = blockIdx.x * 32, k0 = blockIdx.y * 32;
    const int tx = threadIdx.x & 31, ty = threadIdx.x >> 5;
    #pragma unroll
    for (int i = 0; i < 4; ++i)
        t[ty + 8 * i][tx] = W[(size_t)(k0 + ty + 8 * i) * N + n0 + tx];
    __syncthreads();
    #pragma unroll
    for (int i = 0; i < 4; ++i) {
        float x = t[tx][ty + 8 * i];
        bf16 h = __float2bfloat16(x);
        size_t o = (size_t)(n0 + ty + 8 * i) * K + k0 + tx;
        TH[o] = h;
        TL[o] = __float2bfloat16(x - __bfloat162float(h));
    }
}

// =================== mma.sync bf16-split GEMM ===================
// EPI: 2 = +bias,+residual (fp32) ; 3 = +bias -> bf16 h/l ; 4 = +bias,relu -> bf16 h/l
#define AST 40

template<int EPI>
__global__ void __launch_bounds__(256)
gemm_mma(const bf16* __restrict__ Ah, const bf16* __restrict__ Al,
         const bf16* __restrict__ Bh, const bf16* __restrict__ Bl,
         const float* __restrict__ bias, const float* __restrict__ res,
         float* __restrict__ C, bf16* __restrict__ Ch, bf16* __restrict__ Cl,
         int K, int N)
{
    __shared__ bf16 sAh[128 * AST];
    __shared__ bf16 sAl[128 * AST];
    __shared__ bf16 sBh[128 * AST];
    __shared__ bf16 sBl[128 * AST];

    const int tid = threadIdx.x, wid = tid >> 5, lane = tid & 31;
    const int m0 = blockIdx.y * 128, n0 = blockIdx.x * 128;
    const int wm = (wid >> 2) * 64;
    const int wn = (wid & 3) * 32;

    float acc[4][4][4] = {};

    uint4 pah[2], pal[2], pbh[2], pbl[2];

    const bf16* Ahp = Ah + (size_t)m0 * K;
    const bf16* Alp = Al + (size_t)m0 * K;
    const bf16* Bhp = Bh + (size_t)n0 * K;
    const bf16* Blp = Bl + (size_t)n0 * K;

    auto fetch = [&](int k0) {
        #pragma unroll
        for (int it = 0; it < 2; ++it) {
            int idx = tid + it * 256;
            int row = idx >> 2, g = idx & 3;
            size_t go = (size_t)row * K + k0 + g * 8;
            pah[it] = *(const uint4*)(Ahp + go);
            pal[it] = *(const uint4*)(Alp + go);
            pbh[it] = *(const uint4*)(Bhp + go);
            pbl[it] = *(const uint4*)(Blp + go);
        }
    };
    auto stage = [&]() {
        #pragma unroll
        for (int it = 0; it < 2; ++it) {
            int idx = tid + it * 256;
            int row = idx >> 2, g = idx & 3;
            *(uint4*)&sAh[row * AST + g * 8] = pah[it];
            *(uint4*)&sAl[row * AST + g * 8] = pal[it];
            *(uint4*)&sBh[row * AST + g * 8] = pbh[it];
            *(uint4*)&sBl[row * AST + g * 8] = pbl[it];
        }
    };

    const int a_row = wm + (lane & 15);
    const int a_kof = (lane >> 4) << 3;
    const int b_row = wn + ((lane >> 4) << 3) + (lane & 7);
    const int b_kof = ((lane >> 3) & 1) << 3;

    const uint32_t sAh_b = smem_u32(sAh), sAl_b = smem_u32(sAl);
    const uint32_t sBh_b = smem_u32(sBh), sBl_b = smem_u32(sBl);

    fetch(0);
    stage();
    __syncthreads();

    const int ns = K >> 5;
    for (int s = 0; s < ns; ++s) {
        if (s + 1 < ns) fetch((s + 1) << 5);

        #pragma unroll
        for (int kstep = 0; kstep < 2; ++kstep) {
            const int kk = kstep * 16;
            uint32_t afh[4][4], afl[4][4];
            #pragma unroll
            for (int mi = 0; mi < 4; ++mi) {
                uint32_t off = (uint32_t)((a_row + mi * 16) * AST + kk + a_kof) * 2;
                ldsm4(afh[mi], sAh_b + off);
                ldsm4(afl[mi], sAl_b + off);
            }
            uint32_t bfh[2][4], bfl[2][4];
            #pragma unroll
            for (int g = 0; g < 2; ++g) {
                uint32_t off = (uint32_t)((b_row + g * 16) * AST + kk + b_kof) * 2;
                ldsm4(bfh[g], sBh_b + off);
                ldsm4(bfl[g], sBl_b + off);
            }
            #pragma unroll
            for (int mi = 0; mi < 4; ++mi)
                #pragma unroll
                for (int ni = 0; ni < 4; ++ni) {
                    const uint32_t* bh_ = &bfh[ni >> 1][(ni & 1) * 2];
                    const uint32_t* bl_ = &bfl[ni >> 1][(ni & 1) * 2];
                    mma16816(acc[mi][ni], afh[mi], bh_);
                    mma16816(acc[mi][ni], afh[mi], bl_);
                    mma16816(acc[mi][ni], afl[mi], bh_);
                }
        }

        __syncthreads();
        if (s + 1 < ns) {
            stage();
            __syncthreads();
        }
    }

    const int er = lane >> 2, ec = (lane & 3) * 2;
    #pragma unroll
    for (int mi = 0; mi < 4; ++mi) {
        #pragma unroll
        for (int hrow = 0; hrow < 2; ++hrow) {
            int row = m0 + wm + mi * 16 + er + hrow * 8;
            #pragma unroll
            for (int ni = 0; ni < 4; ++ni) {
                int col = n0 + wn + ni * 8 + ec;
                float v0 = acc[mi][ni][hrow * 2 + 0] + bias[col];
                float v1 = acc[mi][ni][hrow * 2 + 1] + bias[col + 1];
                if (EPI == 4) { v0 = fmaxf(v0, 0.0f); v1 = fmaxf(v1, 0.0f); }
                if (EPI == 2) {
                    v0 += res[(size_t)row * N + col];
                    v1 += res[(size_t)row * N + col + 1];
                    float2 o = {v0, v1};
                    *(float2*)(C + (size_t)row * N + col) = o;
                } else {
                    uint32_t hi, lo;
                    split2(v0, v1, hi, lo);
                    *(uint32_t*)(Ch + (size_t)row * N + col) = hi;
                    *(uint32_t*)(Cl + (size_t)row * N + col) = lo;
                }
            }
        }
    }
}

// =================== fused flash attention (q-tile 64, 128 thr) ===============
#define FST 72

__global__ void __launch_bounds__(128)
flash_kernel(const bf16* __restrict__ qkvh, const bf16* __restrict__ qkvl,
             const float* __restrict__ pos, const float* __restrict__ pmask,
             const float* __restrict__ amask, const unsigned char* __restrict__ pad,
             const float* __restrict__ table,
             bf16* __restrict__ ctxh, bf16* __restrict__ ctxl)
{
    __shared__ bf16 sKh[64 * FST], sKl[64 * FST];
    __shared__ bf16 sVh[64 * FST], sVl[64 * FST];
    __shared__ float pxq[64], pyq[64], pmq[64];
    __shared__ float pxk[64], pyk[64], pmk[64], padk[64];

    const int q0 = blockIdx.x * 64;
    const int bh = blockIdx.y;
    const int b = bh / HH, h = bh % HH;
    const int tid = threadIdx.x, wid = tid >> 5, lane = tid & 31;
    const float* tbl = table + (size_t)h * TBL * TBL;

    const bf16* Qh = qkvh + (size_t)(b * LL) * QN + h * DKH;
    const bf16* Ql = qkvl + (size_t)(b * LL) * QN + h * DKH;
    const bf16* Kh = Qh + DD;
    const bf16* Kl = Ql + DD;
    const bf16* Vh = Qh + 2 * DD;
    const bf16* Vl = Ql + 2 * DD;

    if (tid < 64) {
        int l = b * LL + q0 + tid;
        pxq[tid] = pos[2 * (size_t)l];
        pyq[tid] = pos[2 * (size_t)l + 1];
        pmq[tid] = pmask[l];
    }

    // stage Q (reuse K buffers) and load Q fragments to registers
    #pragma unroll
    for (int it = 0; it < 4; ++it) {
        int idx = tid + it * 128;
        int row = idx >> 3, g = idx & 7;
        size_t go = (size_t)(q0 + row) * QN + g * 8;
        *(uint4*)&sKh[row * FST + g * 8] = *(const uint4*)(Qh + go);
        *(uint4*)&sKl[row * FST + g * 8] = *(const uint4*)(Ql + go);
    }
    __syncthreads();

    const uint32_t sKh_b = smem_u32(sKh), sKl_b = smem_u32(sKl);
    const uint32_t sVh_b = smem_u32(sVh), sVl_b = smem_u32(sVl);

    uint32_t qfh[4][4], qfl[4][4];
    {
        int a_row = wid * 16 + (lane & 15);
        int a_kof = (lane >> 4) << 3;
        #pragma unroll
        for (int j = 0; j < 4; ++j) {
            uint32_t off = (uint32_t)(a_row * FST + j * 16 + a_kof) * 2;
            ldsm4(qfh[j], sKh_b + off);
            ldsm4(qfl[j], sKl_b + off);
        }
    }
    __syncthreads();

    const int er = lane >> 2, ec = (lane & 3) * 2;
    const int qr0 = q0 + wid * 16 + er;
    float mrow[2] = {-1e30f, -1e30f}, lrow[2] = {0.f, 0.f};
    float accO[8][4] = {};

    for (int kt = 0; kt < 16; ++kt) {
        const int k0 = kt * 64;
        #pragma unroll
        for (int it = 0; it < 4; ++it) {
            int idx = tid + it * 128;
            int row = idx >> 3, g = idx & 7;
            size_t go = (size_t)(k0 + row) * QN + g * 8;
            *(uint4*)&sKh[row * FST + g * 8] = *(const uint4*)(Kh + go);
            *(uint4*)&sKl[row * FST + g * 8] = *(const uint4*)(Kl + go);
            *(uint4*)&sVh[row * FST + g * 8] = *(const uint4*)(Vh + go);
            *(uint4*)&sVl[row * FST + g * 8] = *(const uint4*)(Vl + go);
        }
        if (tid < 64) {
            int l = b * LL + k0 + tid;
            pxk[tid] = pos[2 * (size_t)l];
            pyk[tid] = pos[2 * (size_t)l + 1];
            pmk[tid] = pmask[l];
            padk[tid] = pad[l] ? 1.f : 0.f;
        }
        __syncthreads();

        // ---- S = Q K^T (3-term split) ----
        float accS[8][4] = {};
        #pragma unroll
        for (int j = 0; j < 4; ++j) {
            #pragma unroll
            for (int g = 0; g < 4; ++g) {
                uint32_t kh[4], kl[4];
                int b_row = g * 16 + ((lane >> 4) << 3) + (lane & 7);
                uint32_t off = (uint32_t)(b_row * FST + j * 16 + (((lane >> 3) & 1) << 3)) * 2;
                ldsm4(kh, sKh_b + off);
                ldsm4(kl, sKl_b + off);
                mma16816(accS[2 * g],     qfh[j], kh);
                mma16816(accS[2 * g],     qfh[j], kl);
                mma16816(accS[2 * g],     qfl[j], kh);
                mma16816(accS[2 * g + 1], qfh[j], kh + 2);
                mma16816(accS[2 * g + 1], qfh[j], kl + 2);
                mma16816(accS[2 * g + 1], qfl[j], kh + 2);
            }
        }

        // ---- bias + mask + online softmax ----
        float pxr[2] = {pxq[wid * 16 + er], pxq[wid * 16 + er + 8]};
        float pyr[2] = {pyq[wid * 16 + er], pyq[wid * 16 + er + 8]};
        float pmr[2] = {pmq[wid * 16 + er], pmq[wid * 16 + er + 8]};
        float newm[2] = {mrow[0], mrow[1]};
        #pragma unroll
        for (int ni = 0; ni < 8; ++ni) {
            #pragma unroll
            for (int r = 0; r < 2; ++r) {
                int kj0 = ni * 8 + ec;
                float2 am = *(const float2*)(amask + (size_t)(b * LL + qr0 + 8 * r) * LL + k0 + kj0);
                #pragma unroll
                for (int u = 0; u < 2; ++u) {
                    int kj = kj0 + u;
                    float s = accS[ni][2 * r + u] * 0.125f;
                    float ddx = fminf(fmaxf(rintf(pxr[r] - pxk[kj]), -(float)MDIST), (float)MDIST);
                    float ddy = fminf(fmaxf(rintf(pyr[r] - pyk[kj]), -(float)MDIST), (float)MDIST);
                    int dx = (int)ddx + MDIST, dy = (int)ddy + MDIST;
                    s += tbl[dy * TBL + dx] * (pmr[r] * pmk[kj]);
                    float amv = (u == 0) ? am.x : am.y;
                    if (amv == 0.f || padk[kj] != 0.f) s = -1e9f;
                    accS[ni][2 * r + u] = s;
                    newm[r] = fmaxf(newm[r], s);
                }
            }
        }
        #pragma unroll
        for (int r = 0; r < 2; ++r) {
            newm[r] = fmaxf(newm[r], __shfl_xor_sync(0xffffffffu, newm[r], 1));
            newm[r] = fmaxf(newm[r], __shfl_xor_sync(0xffffffffu, newm[r], 2));
        }
        float alpha[2], psum[2] = {0.f, 0.f};
        #pragma unroll
        for (int r = 0; r < 2; ++r) {
            alpha[r] = __expf(mrow[r] - newm[r]);
            mrow[r] = newm[r];
        }
        #pragma unroll
        for (int ni = 0; ni < 8; ++ni)
            #pragma unroll
            for (int u = 0; u < 4; ++u) {
                float p = __expf(accS[ni][u] - newm[u >> 1]);
                accS[ni][u] = p;
                psum[u >> 1] += p;
            }
        #pragma unroll
        for (int r = 0; r < 2; ++r) {
            psum[r] += __shfl_xor_sync(0xffffffffu, psum[r], 1);
            psum[r] += __shfl_xor_sync(0xffffffffu, psum[r], 2);
            lrow[r] = lrow[r] * alpha[r] + psum[r];
        }
        #pragma unroll
        for (int ni = 0; ni < 8; ++ni)
            #pragma unroll
            for (int u = 0; u < 4; ++u)
                accO[ni][u] *= alpha[u >> 1];

        // ---- O += P V (3-term split), P frags built in registers ----
        #pragma unroll
        for (int j = 0; j < 4; ++j) {
            uint32_t afh[4], afl[4];
            split2(accS[2 * j][0],     accS[2 * j][1],     afh[0], afl[0]);
            split2(accS[2 * j][2],     accS[2 * j][3],     afh[1], afl[1]);
            split2(accS[2 * j + 1][0], accS[2 * j + 1][1], afh[2], afl[2]);
            split2(accS[2 * j + 1][2], accS[2 * j + 1][3], afh[3], afl[3]);
            #pragma unroll
            for (int g = 0; g < 4; ++g) {
                uint32_t vh[4], vl[4];
                uint32_t off = (uint32_t)((j * 16 + (lane & 15)) * FST + g * 16 + ((lane >> 4) << 3)) * 2;
                ldsm4t(vh, sVh_b + off);
                ldsm4t(vl, sVl_b + off);
                mma16816(accO[2 * g],     afh, vh);
                mma16816(accO[2 * g],     afh, vl);
                mma16816(accO[2 * g],     afl, vh);
                mma16816(accO[2 * g + 1], afh, vh + 2);
                mma16816(accO[2 * g + 1], afh, vl + 2);
                mma16816(accO[2 * g + 1], afl, vh + 2);
            }
        }
        __syncthreads();
    }

    // ---- write ctx (bf16 split) ----
    #pragma unroll
    for (int r = 0; r < 2; ++r) {
        float inv = 1.f / lrow[r];
        #pragma unroll
        for (int ni = 0; ni < 8; ++ni) {
            uint32_t hi, lo;
            split2(accO[ni][2 * r] * inv, accO[ni][2 * r + 1] * inv, hi, lo);
            size_t o = (size_t)(b * LL + qr0 + 8 * r) * DD + h * DKH + ni * 8 + ec;
            *(uint32_t*)(ctxh + o) = hi;
            *(uint32_t*)(ctxl + o) = lo;
        }
    }
}

// ------------- LayerNorm (SPLIT: also emit bf16 h/l) -------------------------
template<bool SPLIT>
__global__ void __launch_bounds__(256)
ln_kernel(const float* __restrict__ X, const float* __restrict__ g,
          const float* __restrict__ bt, float* __restrict__ O,
          bf16* __restrict__ Oh, bf16* __restrict__ Ol)
{
    const int row = blockIdx.x;
    const float* x = X + (size_t)row * DD;
    const int tid = threadIdx.x;

    float v[3];
    #pragma unroll
    for (int i = 0; i < 3; ++i) v[i] = x[tid + i * 256];

    __shared__ float red[256];
    float s = v[0] + v[1] + v[2];
    red[tid] = s; __syncthreads();
    for (int st = 128; st > 0; st >>= 1) {
        if (tid < st) red[tid] += red[tid + st];
        __syncthreads();
    }
    float mean = red[0] * (1.0f / DD);
    __syncthreads();

    float d0 = v[0] - mean, d1 = v[1] - mean, d2 = v[2] - mean;
    red[tid] = d0 * d0 + d1 * d1 + d2 * d2; __syncthreads();
    for (int st = 128; st > 0; st >>= 1) {
        if (tid < st) red[tid] += red[tid + st];
        __syncthreads();
    }
    float var = red[0] * (1.0f / DD);
    float inv = rsqrtf(var + 1e-5f);

    #pragma unroll
    for (int i = 0; i < 3; ++i) {
        int c = tid + i * 256;
        float o = (v[i] - mean) * inv * g[c] + bt[c];
        O[(size_t)row * DD + c] = o;
        if (SPLIT) {
            bf16 h = __float2bfloat16(o);
            Oh[(size_t)row * DD + c] = h;
            Ol[(size_t)row * DD + c] = __float2bfloat16(o - __bfloat162float(h));
        }
    }
}

// ------------------------------- launch ---------------------------------------
extern "C" void kernel_launch(void* const* d_in, const int* in_sizes, int n_in,
                              void* d_out, int out_size)
{
    const float* tokens = (const float*)d_in[0];
    const float* pos    = (const float*)d_in[1];
    const float* pmask  = (const float*)d_in[2];
    const float* amask  = (const float*)d_in[3];
    const unsigned char* pad = (const unsigned char*)d_in[4];
    const float* Wq = (const float*)d_in[5];
    const float* bq = (const float*)d_in[6];
    const float* Wk = (const float*)d_in[7];
    const float* bk = (const float*)d_in[8];
    const float* Wv = (const float*)d_in[9];
    const float* bv = (const float*)d_in[10];
    const float* Wo = (const float*)d_in[11];
    const float* bo = (const float*)d_in[12];
    const float* table = (const float*)d_in[13];
    const float* W1 = (const float*)d_in[14];
    const float* b1 = (const float*)d_in[15];
    const float* W2 = (const float*)d_in[16];
    const float* b2 = (const float*)d_in[17];
    const float* ln1g = (const float*)d_in[18];
    const float* ln1b = (const float*)d_in[19];
    const float* ln2g = (const float*)d_in[20];
    const float* ln2b = (const float*)d_in[21];
    float* out = (float*)d_out;

    float *Pb, *Tb, *bqkv;
    cudaGetSymbolAddress((void**)&Pb, g_pre);
    cudaGetSymbolAddress((void**)&Tb, g_t1);
    cudaGetSymbolAddress((void**)&bqkv, g_bqkv);

    bf16 *tokh, *tokl, *qkvh, *qkvl, *ctxh, *ctxl, *t1h, *t1l, *ffh, *ffl;
    cudaGetSymbolAddress((void**)&tokh, g_tokh); cudaGetSymbolAddress((void**)&tokl, g_tokl);
    cudaGetSymbolAddress((void**)&qkvh, g_qkvh); cudaGetSymbolAddress((void**)&qkvl, g_qkvl);
    cudaGetSymbolAddress((void**)&ctxh, g_ctxh); cudaGetSymbolAddress((void**)&ctxl, g_ctxl);
    cudaGetSymbolAddress((void**)&t1h, g_t1h);   cudaGetSymbolAddress((void**)&t1l, g_t1l);
    cudaGetSymbolAddress((void**)&ffh, g_ffh);   cudaGetSymbolAddress((void**)&ffl, g_ffl);

    bf16 *wqkvh, *wqkvl, *woh, *wol, *w1h, *w1l, *w2h, *w2l;
    cudaGetSymbolAddress((void**)&wqkvh, g_wqkvh); cudaGetSymbolAddress((void**)&wqkvl, g_wqkvl);
    cudaGetSymbolAddress((void**)&woh, g_woh); cudaGetSymbolAddress((void**)&wol, g_wol);
    cudaGetSymbolAddress((void**)&w1h, g_w1h); cudaGetSymbolAddress((void**)&w1l, g_w1l);
    cudaGetSymbolAddress((void**)&w2h, g_w2h); cudaGetSymbolAddress((void**)&w2l, g_w2l);

    // Launch 1: all four D×D weight transposes (Wq/Wk/Wv/Wo)
    cvt_wT4<<<dim3(DD / 32, DD / 32, 4), 256>>>(Wq, Wk, Wv, Wo, wqkvh, wqkvl, woh, wol);
    // Launches 2-3: FFN weights
    cvt_wT<<<dim3(FF / 32, DD / 32), 256>>>(W1, w1h, w1l, DD, FF);
    cvt_wT<<<dim3(DD / 32, FF / 32), 256>>>(W2, w2h, w2l, FF, DD);
    // Launch 4: tokens split + QKV bias concat (extra trailing blocks)
    {
        int n4 = BL * DD / 4;
        int nblk = (n4 + QN + 255) / 256;
        cvt_split_bias<<<nblk, 256>>>(tokens, tokh, tokl, n4, bq, bk, bv, bqkv);
    }

    // Launch 5: fused QKV GEMM -> bf16 split [BL, 2304]
    gemm_mma<3><<<dim3(QN / 128, BL / 128), 256>>>(tokh, tokl, wqkvh, wqkvl, bqkv,
                                                   nullptr, nullptr, qkvh, qkvl, DD, QN);

    // Launch 6: fused attention  <-- ncu -s 5 -c 1 captures THIS
    dim3 gfa(LL / 64, BB * HH);
    flash_kernel<<<gfa, 128>>>(qkvh, qkvl, pos, pmask, amask, pad, table, ctxh, ctxl);

    // out proj + residual -> fp32, LN1 (emits fp32 + bf16 split)
    gemm_mma<2><<<dim3(DD / 128, BL / 128), 256>>>(ctxh, ctxl, woh, wol, bo,
                                                   tokens, Pb, nullptr, nullptr, DD, DD);
    ln_kernel<true><<<BL, 256>>>(Pb, ln1g, ln1b, Tb, t1h, t1l);

    // FFN
    gemm_mma<4><<<dim3(FF / 128, BL / 128), 256>>>(t1h, t1l, w1h, w1l, b1,
                                                   nullptr, nullptr, ffh, ffl, DD, FF);
    gemm_mma<2><<<dim3(DD / 128, BL / 128), 256>>>(ffh, ffl, w2h, w2l, b2,
                                                   Tb, Pb, nullptr, nullptr, FF, DD);
    ln_kernel<false><<<BL, 256>>>(Pb, ln2g, ln2b, out, nullptr, nullptr);
}

// round 12
// speedup vs baseline: 1.6315x; 1.6173x over previous
#include <cuda_runtime.h>
#include <cuda_fp16.h>
#include <math.h>
#include <stdint.h>

#define BB   4
#define LL   1024
#define BL   4096
#define DD   768
#define HH   12
#define DKH  64
#define FF   3072
#define MDIST 100
#define TBL  201
#define QN   2304   // combined QKV width

typedef __half fp16;

// ---------------- scratch ----------------
__device__ float g_pre[BL * DD];
__device__ float g_t1[BL * DD];
__device__ float g_bqkv[QN];

__device__ __align__(16) fp16 g_tokh[BL * DD];
__device__ __align__(16) fp16 g_qkvh[(size_t)BL * QN], g_qkvl[(size_t)BL * QN];
__device__ __align__(16) fp16 g_ctxh[BL * DD];
__device__ __align__(16) fp16 g_t1h[BL * DD];
__device__ __align__(16) fp16 g_ffh[(size_t)BL * FF];

__device__ __align__(16) fp16 g_wqkvh[(size_t)QN * DD], g_wqkvl[(size_t)QN * DD];
__device__ __align__(16) fp16 g_woh[DD * DD], g_wol[DD * DD];
__device__ __align__(16) fp16 g_w1h[(size_t)DD * FF], g_w1l[(size_t)DD * FF];
__device__ __align__(16) fp16 g_w2h[(size_t)DD * FF], g_w2l[(size_t)DD * FF];

// =================== helpers ===================
__device__ __forceinline__ uint32_t smem_u32(const void* p) {
    uint32_t a;
    asm("{ .reg .u64 t; cvta.to.shared.u64 t, %1; cvt.u32.u64 %0, t; }" : "=r"(a) : "l"(p));
    return a;
}
__device__ __forceinline__ void ldsm4(uint32_t* r, uint32_t addr) {
    asm volatile("ldmatrix.sync.aligned.m8n8.x4.shared.b16 {%0,%1,%2,%3}, [%4];"
        : "=r"(r[0]), "=r"(r[1]), "=r"(r[2]), "=r"(r[3]) : "r"(addr));
}
__device__ __forceinline__ void ldsm4t(uint32_t* r, uint32_t addr) {
    asm volatile("ldmatrix.sync.aligned.m8n8.x4.trans.shared.b16 {%0,%1,%2,%3}, [%4];"
        : "=r"(r[0]), "=r"(r[1]), "=r"(r[2]), "=r"(r[3]) : "r"(addr));
}
__device__ __forceinline__ void mma16816(float* d, const uint32_t* a, const uint32_t* b) {
    asm volatile("mma.sync.aligned.m16n8k16.row.col.f32.f16.f16.f32 "
        "{%0,%1,%2,%3}, {%4,%5,%6,%7}, {%8,%9}, {%0,%1,%2,%3};"
        : "+f"(d[0]), "+f"(d[1]), "+f"(d[2]), "+f"(d[3])
        : "r"(a[0]), "r"(a[1]), "r"(a[2]), "r"(a[3]), "r"(b[0]), "r"(b[1]));
}
__device__ __forceinline__ uint32_t pack2h(float a, float b) {
    __half2 h = __floats2half2_rn(a, b);
    return *(uint32_t*)&h;
}
__device__ __forceinline__ void split2h(float a, float b, uint32_t& hi, uint32_t& lo) {
    __half2 h = __floats2half2_rn(a, b);
    float2 hf = __half22float2(h);
    __half2 l = __floats2half2_rn(a - hf.x, b - hf.y);
    hi = *(uint32_t*)&h;
    lo = *(uint32_t*)&l;
}

// =================== conversions ===================
// tokens -> single fp16 ; trailing blocks concat QKV bias
__global__ void __launch_bounds__(256)
cvt_split_bias(const float* __restrict__ X, fp16* __restrict__ H,
               int n4, const float* __restrict__ bq, const float* __restrict__ bk,
               const float* __restrict__ bv, float* __restrict__ bqkv)
{
    int i = blockIdx.x * 256 + threadIdx.x;
    if (i < n4) {
        float4 v = ((const float4*)X)[i];
        uint2 hh = {pack2h(v.x, v.y), pack2h(v.z, v.w)};
        ((uint2*)H)[i] = hh;
        return;
    }
    int j = i - n4;
    if (j < DD)           bqkv[j] = bq[j];
    else if (j < 2 * DD)  bqkv[j] = bk[j - DD];
    else if (j < 3 * DD)  bqkv[j] = bv[j - 2 * DD];
}

// 4 D×D weight transposes (hi/lo fp16): z=0..2 QKV slices, z=3 Wo
__global__ void __launch_bounds__(256)
cvt_wT4(const float* __restrict__ Wq, const float* __restrict__ Wk,
        const float* __restrict__ Wv, const float* __restrict__ Wo,
        fp16* __restrict__ qkvTH, fp16* __restrict__ qkvTL,
        fp16* __restrict__ oTH, fp16* __restrict__ oTL)
{
    __shared__ float t[32][33];
    const int z = blockIdx.z;
    const float* W = (z == 0) ? Wq : (z == 1) ? Wk : (z == 2) ? Wv : Wo;
    fp16* TH = (z < 3) ? (qkvTH + (size_t)z * DD * DD) : oTH;
    fp16* TL = (z < 3) ? (qkvTL + (size_t)z * DD * DD) : oTL;

    const int n0 = blockIdx.x * 32, k0 = blockIdx.y * 32;
    const int tx = threadIdx.x & 31, ty = threadIdx.x >> 5;
    #pragma unroll
    for (int i = 0; i < 4; ++i)
        t[ty + 8 * i][tx] = W[(size_t)(k0 + ty + 8 * i) * DD + n0 + tx];
    __syncthreads();
    #pragma unroll
    for (int i = 0; i < 4; ++i) {
        float x = t[tx][ty + 8 * i];
        fp16 h = __float2half_rn(x);
        size_t o = (size_t)(n0 + ty + 8 * i) * DD + k0 + tx;
        TH[o] = h;
        TL[o] = __float2half_rn(x - __half2float(h));
    }
}

__global__ void __launch_bounds__(256)
cvt_wT(const float* __restrict__ W, fp16* __restrict__ TH, fp16* __restrict__ TL, int K, int N)
{
    __shared__ float t[32][33];
    const int n0 = blockIdx.x * 32, k0 = blockIdx.y * 32;
    const int tx = threadIdx.x & 31, ty = threadIdx.x >> 5;
    #pragma unroll
    for (int i = 0; i < 4; ++i)
        t[ty + 8 * i][tx] = W[(size_t)(k0 + ty + 8 * i) * N + n0 + tx];
    __syncthreads();
    #pragma unroll
    for (int i = 0; i < 4; ++i) {
        float x = t[tx][ty + 8 * i];
        fp16 h = __float2half_rn(x);
        size_t o = (size_t)(n0 + ty + 8 * i) * K + k0 + tx;
        TH[o] = h;
        TL[o] = __float2half_rn(x - __half2float(h));
    }
}

// =================== mma.sync fp16 2-term GEMM ===================
// C = A(fp16)[M,K] @ (Bh+Bl)^T ; B pre-transposed [N][K] hi/lo
// EPI: 2 = +bias,+residual (fp32 out) ; 3 = +bias -> fp16 h/l (lo only for col>=DD)
//      4 = +bias,relu -> fp16 single
#define AST 40

template<int EPI>
__global__ void __launch_bounds__(256)
gemm_mma(const fp16* __restrict__ A,
         const fp16* __restrict__ Bh, const fp16* __restrict__ Bl,
         const float* __restrict__ bias, const float* __restrict__ res,
         float* __restrict__ C, fp16* __restrict__ Ch, fp16* __restrict__ Cl,
         int K, int N)
{
    __shared__ fp16 sA [128 * AST];
    __shared__ fp16 sBh[128 * AST];
    __shared__ fp16 sBl[128 * AST];

    const int tid = threadIdx.x, wid = tid >> 5, lane = tid & 31;
    const int m0 = blockIdx.y * 128, n0 = blockIdx.x * 128;
    const int wm = (wid >> 2) * 64;
    const int wn = (wid & 3) * 32;

    float acc[4][4][4] = {};

    uint4 pa[2], pbh[2], pbl[2];

    const fp16* Ap  = A  + (size_t)m0 * K;
    const fp16* Bhp = Bh + (size_t)n0 * K;
    const fp16* Blp = Bl + (size_t)n0 * K;

    auto fetch = [&](int k0) {
        #pragma unroll
        for (int it = 0; it < 2; ++it) {
            int idx = tid + it * 256;
            int row = idx >> 2, g = idx & 3;
            size_t go = (size_t)row * K + k0 + g * 8;
            pa[it]  = *(const uint4*)(Ap + go);
            pbh[it] = *(const uint4*)(Bhp + go);
            pbl[it] = *(const uint4*)(Blp + go);
        }
    };
    auto stage = [&]() {
        #pragma unroll
        for (int it = 0; it < 2; ++it) {
            int idx = tid + it * 256;
            int row = idx >> 2, g = idx & 3;
            *(uint4*)&sA [row * AST + g * 8] = pa[it];
            *(uint4*)&sBh[row * AST + g * 8] = pbh[it];
            *(uint4*)&sBl[row * AST + g * 8] = pbl[it];
        }
    };

    const int a_row = wm + (lane & 15);
    const int a_kof = (lane >> 4) << 3;
    const int b_row = wn + ((lane >> 4) << 3) + (lane & 7);
    const int b_kof = ((lane >> 3) & 1) << 3;

    const uint32_t sA_b = smem_u32(sA);
    const uint32_t sBh_b = smem_u32(sBh), sBl_b = smem_u32(sBl);

    fetch(0);
    stage();
    __syncthreads();

    const int ns = K >> 5;
    for (int s = 0; s < ns; ++s) {
        if (s + 1 < ns) fetch((s + 1) << 5);

        #pragma unroll
        for (int kstep = 0; kstep < 2; ++kstep) {
            const int kk = kstep * 16;
            uint32_t af[4][4];
            #pragma unroll
            for (int mi = 0; mi < 4; ++mi) {
                uint32_t off = (uint32_t)((a_row + mi * 16) * AST + kk + a_kof) * 2;
                ldsm4(af[mi], sA_b + off);
            }
            uint32_t bfh[2][4], bfl[2][4];
            #pragma unroll
            for (int g = 0; g < 2; ++g) {
                uint32_t off = (uint32_t)((b_row + g * 16) * AST + kk + b_kof) * 2;
                ldsm4(bfh[g], sBh_b + off);
                ldsm4(bfl[g], sBl_b + off);
            }
            #pragma unroll
            for (int mi = 0; mi < 4; ++mi)
                #pragma unroll
                for (int ni = 0; ni < 4; ++ni) {
                    const uint32_t* bh_ = &bfh[ni >> 1][(ni & 1) * 2];
                    const uint32_t* bl_ = &bfl[ni >> 1][(ni & 1) * 2];
                    mma16816(acc[mi][ni], af[mi], bh_);
                    mma16816(acc[mi][ni], af[mi], bl_);
                }
        }

        __syncthreads();
        if (s + 1 < ns) {
            stage();
            __syncthreads();
        }
    }

    const int er = lane >> 2, ec = (lane & 3) * 2;
    #pragma unroll
    for (int mi = 0; mi < 4; ++mi) {
        #pragma unroll
        for (int hrow = 0; hrow < 2; ++hrow) {
            int row = m0 + wm + mi * 16 + er + hrow * 8;
            #pragma unroll
            for (int ni = 0; ni < 4; ++ni) {
                int col = n0 + wn + ni * 8 + ec;
                float v0 = acc[mi][ni][hrow * 2 + 0] + bias[col];
                float v1 = acc[mi][ni][hrow * 2 + 1] + bias[col + 1];
                if (EPI == 4) { v0 = fmaxf(v0, 0.0f); v1 = fmaxf(v1, 0.0f); }
                if (EPI == 2) {
                    v0 += res[(size_t)row * N + col];
                    v1 += res[(size_t)row * N + col + 1];
                    float2 o = {v0, v1};
                    *(float2*)(C + (size_t)row * N + col) = o;
                } else if (EPI == 3) {
                    uint32_t hi, lo;
                    split2h(v0, v1, hi, lo);
                    *(uint32_t*)(Ch + (size_t)row * N + col) = hi;
                    if (col >= DD)   // only K/V need lo
                        *(uint32_t*)(Cl + (size_t)row * N + col) = lo;
                } else {             // EPI == 4: single fp16
                    *(uint32_t*)(Ch + (size_t)row * N + col) = pack2h(v0, v1);
                }
            }
        }
    }
}

// =================== fused flash attention (q-tile 64, 128 thr) ===============
// Q: single fp16 ; K,V: hi/lo 2-term
#define FST 72

__global__ void __launch_bounds__(128)
flash_kernel(const fp16* __restrict__ qkvh, const fp16* __restrict__ qkvl,
             const float* __restrict__ pos, const float* __restrict__ pmask,
             const float* __restrict__ amask, const unsigned char* __restrict__ pad,
             const float* __restrict__ table, fp16* __restrict__ ctxh)
{
    __shared__ fp16 sKh[64 * FST], sKl[64 * FST];
    __shared__ fp16 sVh[64 * FST], sVl[64 * FST];
    __shared__ float pxq[64], pyq[64], pmq[64];
    __shared__ float pxk[64], pyk[64], pmk[64], padk[64];

    const int q0 = blockIdx.x * 64;
    const int bh = blockIdx.y;
    const int b = bh / HH, h = bh % HH;
    const int tid = threadIdx.x, wid = tid >> 5, lane = tid & 31;
    const float* tbl = table + (size_t)h * TBL * TBL;

    const fp16* Qh = qkvh + (size_t)(b * LL) * QN + h * DKH;
    const fp16* Kh = Qh + DD;
    const fp16* Kl = qkvl + (size_t)(b * LL) * QN + h * DKH + DD;
    const fp16* Vh = Qh + 2 * DD;
    const fp16* Vl = Kl + DD;

    if (tid < 64) {
        int l = b * LL + q0 + tid;
        pxq[tid] = pos[2 * (size_t)l];
        pyq[tid] = pos[2 * (size_t)l + 1];
        pmq[tid] = pmask[l];
    }

    // stage Q (reuse K buffer) and load Q fragments to registers
    #pragma unroll
    for (int it = 0; it < 4; ++it) {
        int idx = tid + it * 128;
        int row = idx >> 3, g = idx & 7;
        size_t go = (size_t)(q0 + row) * QN + g * 8;
        *(uint4*)&sKh[row * FST + g * 8] = *(const uint4*)(Qh + go);
    }
    __syncthreads();

    const uint32_t sKh_b = smem_u32(sKh), sKl_b = smem_u32(sKl);
    const uint32_t sVh_b = smem_u32(sVh), sVl_b = smem_u32(sVl);

    uint32_t qf[4][4];
    {
        int a_row = wid * 16 + (lane & 15);
        int a_kof = (lane >> 4) << 3;
        #pragma unroll
        for (int j = 0; j < 4; ++j) {
            uint32_t off = (uint32_t)(a_row * FST + j * 16 + a_kof) * 2;
            ldsm4(qf[j], sKh_b + off);
        }
    }
    __syncthreads();

    const int er = lane >> 2, ec = (lane & 3) * 2;
    const int qr0 = q0 + wid * 16 + er;
    float mrow[2] = {-1e30f, -1e30f}, lrow[2] = {0.f, 0.f};
    float accO[8][4] = {};

    for (int kt = 0; kt < 16; ++kt) {
        const int k0 = kt * 64;
        #pragma unroll
        for (int it = 0; it < 4; ++it) {
            int idx = tid + it * 128;
            int row = idx >> 3, g = idx & 7;
            size_t go = (size_t)(k0 + row) * QN + g * 8;
            *(uint4*)&sKh[row * FST + g * 8] = *(const uint4*)(Kh + go);
            *(uint4*)&sKl[row * FST + g * 8] = *(const uint4*)(Kl + go);
            *(uint4*)&sVh[row * FST + g * 8] = *(const uint4*)(Vh + go);
            *(uint4*)&sVl[row * FST + g * 8] = *(const uint4*)(Vl + go);
        }
        if (tid < 64) {
            int l = b * LL + k0 + tid;
            pxk[tid] = pos[2 * (size_t)l];
            pyk[tid] = pos[2 * (size_t)l + 1];
            pmk[tid] = pmask[l];
            padk[tid] = pad[l] ? 1.f : 0.f;
        }
        __syncthreads();

        // ---- S = Q (Kh + Kl)^T : 2-term ----
        float accS[8][4] = {};
        #pragma unroll
        for (int j = 0; j < 4; ++j) {
            #pragma unroll
            for (int g = 0; g < 4; ++g) {
                uint32_t kh[4], kl[4];
                int b_row = g * 16 + ((lane >> 4) << 3) + (lane & 7);
                uint32_t off = (uint32_t)(b_row * FST + j * 16 + (((lane >> 3) & 1) << 3)) * 2;
                ldsm4(kh, sKh_b + off);
                ldsm4(kl, sKl_b + off);
                mma16816(accS[2 * g],     qf[j], kh);
                mma16816(accS[2 * g],     qf[j], kl);
                mma16816(accS[2 * g + 1], qf[j], kh + 2);
                mma16816(accS[2 * g + 1], qf[j], kl + 2);
            }
        }

        // ---- bias + mask + online softmax ----
        float pxr[2] = {pxq[wid * 16 + er], pxq[wid * 16 + er + 8]};
        float pyr[2] = {pyq[wid * 16 + er], pyq[wid * 16 + er + 8]};
        float pmr[2] = {pmq[wid * 16 + er], pmq[wid * 16 + er + 8]};
        float newm[2] = {mrow[0], mrow[1]};
        #pragma unroll
        for (int ni = 0; ni < 8; ++ni) {
            #pragma unroll
            for (int r = 0; r < 2; ++r) {
                int kj0 = ni * 8 + ec;
                float2 am = *(const float2*)(amask + (size_t)(b * LL + qr0 + 8 * r) * LL + k0 + kj0);
                #pragma unroll
                for (int u = 0; u < 2; ++u) {
                    int kj = kj0 + u;
                    float s = accS[ni][2 * r + u] * 0.125f;
                    float ddx = fminf(fmaxf(rintf(pxr[r] - pxk[kj]), -(float)MDIST), (float)MDIST);
                    float ddy = fminf(fmaxf(rintf(pyr[r] - pyk[kj]), -(float)MDIST), (float)MDIST);
                    int dx = (int)ddx + MDIST, dy = (int)ddy + MDIST;
                    s += tbl[dy * TBL + dx] * (pmr[r] * pmk[kj]);
                    float amv = (u == 0) ? am.x : am.y;
                    if (amv == 0.f || padk[kj] != 0.f) s = -1e9f;
                    accS[ni][2 * r + u] = s;
                    newm[r] = fmaxf(newm[r], s);
                }
            }
        }
        #pragma unroll
        for (int r = 0; r < 2; ++r) {
            newm[r] = fmaxf(newm[r], __shfl_xor_sync(0xffffffffu, newm[r], 1));
            newm[r] = fmaxf(newm[r], __shfl_xor_sync(0xffffffffu, newm[r], 2));
        }
        float alpha[2], psum[2] = {0.f, 0.f};
        #pragma unroll
        for (int r = 0; r < 2; ++r) {
            alpha[r] = __expf(mrow[r] - newm[r]);
            mrow[r] = newm[r];
        }
        #pragma unroll
        for (int ni = 0; ni < 8; ++ni)
            #pragma unroll
            for (int u = 0; u < 4; ++u) {
                float p = __expf(accS[ni][u] - newm[u >> 1]);
                accS[ni][u] = p;
                psum[u >> 1] += p;
            }
        #pragma unroll
        for (int r = 0; r < 2; ++r) {
            psum[r] += __shfl_xor_sync(0xffffffffu, psum[r], 1);
            psum[r] += __shfl_xor_sync(0xffffffffu, psum[r], 2);
            lrow[r] = lrow[r] * alpha[r] + psum[r];
        }
        #pragma unroll
        for (int ni = 0; ni < 8; ++ni)
            #pragma unroll
            for (int u = 0; u < 4; ++u)
                accO[ni][u] *= alpha[u >> 1];

        // ---- O += P (Vh + Vl) : P single fp16, 2-term ----
        #pragma unroll
        for (int j = 0; j < 4; ++j) {
            uint32_t af[4];
            af[0] = pack2h(accS[2 * j][0],     accS[2 * j][1]);
            af[1] = pack2h(accS[2 * j][2],     accS[2 * j][3]);
            af[2] = pack2h(accS[2 * j + 1][0], accS[2 * j + 1][1]);
            af[3] = pack2h(accS[2 * j + 1][2], accS[2 * j + 1][3]);
            #pragma unroll
            for (int g = 0; g < 4; ++g) {
                uint32_t vh[4], vl[4];
                uint32_t off = (uint32_t)((j * 16 + (lane & 15)) * FST + g * 16 + ((lane >> 4) << 3)) * 2;
                ldsm4t(vh, sVh_b + off);
                ldsm4t(vl, sVl_b + off);
                mma16816(accO[2 * g],     af, vh);
                mma16816(accO[2 * g],     af, vl);
                mma16816(accO[2 * g + 1], af, vh + 2);
                mma16816(accO[2 * g + 1], af, vl + 2);
            }
        }
        __syncthreads();
    }

    // ---- write ctx (single fp16) ----
    #pragma unroll
    for (int r = 0; r < 2; ++r) {
        float inv = 1.f / lrow[r];
        #pragma unroll
        for (int ni = 0; ni < 8; ++ni) {
            size_t o = (size_t)(b * LL + qr0 + 8 * r) * DD + h * DKH + ni * 8 + ec;
            *(uint32_t*)(ctxh + o) = pack2h(accO[ni][2 * r] * inv, accO[ni][2 * r + 1] * inv);
        }
    }
}

// ------------- LayerNorm (SPLIT: also emit single fp16) ----------------------
template<bool SPLIT>
__global__ void __launch_bounds__(256)
ln_kernel(const float* __restrict__ X, const float* __restrict__ g,
          const float* __restrict__ bt, float* __restrict__ O,
          fp16* __restrict__ Oh)
{
    const int row = blockIdx.x;
    const float* x = X + (size_t)row * DD;
    const int tid = threadIdx.x;

    float v[3];
    #pragma unroll
    for (int i = 0; i < 3; ++i) v[i] = x[tid + i * 256];

    __shared__ float red[256];
    float s = v[0] + v[1] + v[2];
    red[tid] = s; __syncthreads();
    for (int st = 128; st > 0; st >>= 1) {
        if (tid < st) red[tid] += red[tid + st];
        __syncthreads();
    }
    float mean = red[0] * (1.0f / DD);
    __syncthreads();

    float d0 = v[0] - mean, d1 = v[1] - mean, d2 = v[2] - mean;
    red[tid] = d0 * d0 + d1 * d1 + d2 * d2; __syncthreads();
    for (int st = 128; st > 0; st >>= 1) {
        if (tid < st) red[tid] += red[tid + st];
        __syncthreads();
    }
    float var = red[0] * (1.0f / DD);
    float inv = rsqrtf(var + 1e-5f);

    #pragma unroll
    for (int i = 0; i < 3; ++i) {
        int c = tid + i * 256;
        float o = (v[i] - mean) * inv * g[c] + bt[c];
        O[(size_t)row * DD + c] = o;
        if (SPLIT) Oh[(size_t)row * DD + c] = __float2half_rn(o);
    }
}

// ------------------------------- launch ---------------------------------------
extern "C" void kernel_launch(void* const* d_in, const int* in_sizes, int n_in,
                              void* d_out, int out_size)
{
    const float* tokens = (const float*)d_in[0];
    const float* pos    = (const float*)d_in[1];
    const float* pmask  = (const float*)d_in[2];
    const float* amask  = (const float*)d_in[3];
    const unsigned char* pad = (const unsigned char*)d_in[4];
    const float* Wq = (const float*)d_in[5];
    const float* bq = (const float*)d_in[6];
    const float* Wk = (const float*)d_in[7];
    const float* bk = (const float*)d_in[8];
    const float* Wv = (const float*)d_in[9];
    const float* bv = (const float*)d_in[10];
    const float* Wo = (const float*)d_in[11];
    const float* bo = (const float*)d_in[12];
    const float* table = (const float*)d_in[13];
    const float* W1 = (const float*)d_in[14];
    const float* b1 = (const float*)d_in[15];
    const float* W2 = (const float*)d_in[16];
    const float* b2 = (const float*)d_in[17];
    const float* ln1g = (const float*)d_in[18];
    const float* ln1b = (const float*)d_in[19];
    const float* ln2g = (const float*)d_in[20];
    const float* ln2b = (const float*)d_in[21];
    float* out = (float*)d_out;

    float *Pb, *Tb, *bqkv;
    cudaGetSymbolAddress((void**)&Pb, g_pre);
    cudaGetSymbolAddress((void**)&Tb, g_t1);
    cudaGetSymbolAddress((void**)&bqkv, g_bqkv);

    fp16 *tokh, *qkvh, *qkvl, *ctxh, *t1h, *ffh;
    cudaGetSymbolAddress((void**)&tokh, g_tokh);
    cudaGetSymbolAddress((void**)&qkvh, g_qkvh); cudaGetSymbolAddress((void**)&qkvl, g_qkvl);
    cudaGetSymbolAddress((void**)&ctxh, g_ctxh);
    cudaGetSymbolAddress((void**)&t1h, g_t1h);
    cudaGetSymbolAddress((void**)&ffh, g_ffh);

    fp16 *wqkvh, *wqkvl, *woh, *wol, *w1h, *w1l, *w2h, *w2l;
    cudaGetSymbolAddress((void**)&wqkvh, g_wqkvh); cudaGetSymbolAddress((void**)&wqkvl, g_wqkvl);
    cudaGetSymbolAddress((void**)&woh, g_woh); cudaGetSymbolAddress((void**)&wol, g_wol);
    cudaGetSymbolAddress((void**)&w1h, g_w1h); cudaGetSymbolAddress((void**)&w1l, g_w1l);
    cudaGetSymbolAddress((void**)&w2h, g_w2h); cudaGetSymbolAddress((void**)&w2l, g_w2l);

    // prep
    cvt_wT4<<<dim3(DD / 32, DD / 32, 4), 256>>>(Wq, Wk, Wv, Wo, wqkvh, wqkvl, woh, wol);
    cvt_wT<<<dim3(FF / 32, DD / 32), 256>>>(W1, w1h, w1l, DD, FF);
    cvt_wT<<<dim3(DD / 32, FF / 32), 256>>>(W2, w2h, w2l, FF, DD);
    {
        int n4 = BL * DD / 4;
        int nblk = (n4 + QN + 255) / 256;
        cvt_split_bias<<<nblk, 256>>>(tokens, tokh, n4, bq, bk, bv, bqkv);
    }

    // fused QKV GEMM -> fp16 (Q: hi only; K,V: hi/lo)
    gemm_mma<3><<<dim3(QN / 128, BL / 128), 256>>>(tokh, wqkvh, wqkvl, bqkv,
                                                   nullptr, nullptr, qkvh, qkvl, DD, QN);

    // fused attention -> ctx fp16
    dim3 gfa(LL / 64, BB * HH);
    flash_kernel<<<gfa, 128>>>(qkvh, qkvl, pos, pmask, amask, pad, table, ctxh);

    // out proj + residual -> fp32, LN1 (emits fp32 + fp16)
    gemm_mma<2><<<dim3(DD / 128, BL / 128), 256>>>(ctxh, woh, wol, bo,
                                                   tokens, Pb, nullptr, nullptr, DD, DD);
    ln_kernel<true><<<BL, 256>>>(Pb, ln1g, ln1b, Tb, t1h);

    // FFN
    gemm_mma<4><<<dim3(FF / 128, BL / 128), 256>>>(t1h, w1h, w1l, b1,
                                                   nullptr, nullptr, ffh, nullptr, DD, FF);
    gemm_mma<2><<<dim3(DD / 128, BL / 128), 256>>>(ffh, w2h, w2l, b2,
                                                   Tb, Pb, nullptr, nullptr, FF, DD);
    ln_kernel<false><<<BL, 256>>>(Pb, ln2g, ln2b, out, nullptr);
}

// round 13
// speedup vs baseline: 1.8006x; 1.1037x over previous
#include <cuda_runtime.h>
#include <cuda_fp16.h>
#include <math.h>
#include <stdint.h>

#define BB   4
#define LL   1024
#define BL   4096
#define DD   768
#define HH   12
#define DKH  64
#define FF   3072
#define MDIST 100
#define TBL  201
#define QN   2304   // combined QKV width

typedef __half fp16;

// ---------------- scratch ----------------
__device__ float g_pre[BL * DD];
__device__ float g_t1[BL * DD];
__device__ float g_bqkv[QN];

__device__ __align__(16) fp16 g_tokh[BL * DD];
__device__ __align__(16) fp16 g_qkvh[(size_t)BL * QN];
__device__ __align__(16) fp16 g_ctxh[BL * DD];
__device__ __align__(16) fp16 g_t1h[BL * DD];
__device__ __align__(16) fp16 g_ffh[(size_t)BL * FF];

__device__ __align__(16) fp16 g_wqkvh[(size_t)QN * DD], g_wqkvl[(size_t)QN * DD];
__device__ __align__(16) fp16 g_woh[DD * DD], g_wol[DD * DD];
__device__ __align__(16) fp16 g_w1h[(size_t)DD * FF], g_w1l[(size_t)DD * FF];
__device__ __align__(16) fp16 g_w2h[(size_t)DD * FF], g_w2l[(size_t)DD * FF];

// =================== helpers ===================
__device__ __forceinline__ uint32_t smem_u32(const void* p) {
    uint32_t a;
    asm("{ .reg .u64 t; cvta.to.shared.u64 t, %1; cvt.u32.u64 %0, t; }" : "=r"(a) : "l"(p));
    return a;
}
__device__ __forceinline__ void ldsm4(uint32_t* r, uint32_t addr) {
    asm volatile("ldmatrix.sync.aligned.m8n8.x4.shared.b16 {%0,%1,%2,%3}, [%4];"
        : "=r"(r[0]), "=r"(r[1]), "=r"(r[2]), "=r"(r[3]) : "r"(addr));
}
__device__ __forceinline__ void ldsm4t(uint32_t* r, uint32_t addr) {
    asm volatile("ldmatrix.sync.aligned.m8n8.x4.trans.shared.b16 {%0,%1,%2,%3}, [%4];"
        : "=r"(r[0]), "=r"(r[1]), "=r"(r[2]), "=r"(r[3]) : "r"(addr));
}
__device__ __forceinline__ void mma16816(float* d, const uint32_t* a, const uint32_t* b) {
    asm volatile("mma.sync.aligned.m16n8k16.row.col.f32.f16.f16.f32 "
        "{%0,%1,%2,%3}, {%4,%5,%6,%7}, {%8,%9}, {%0,%1,%2,%3};"
        : "+f"(d[0]), "+f"(d[1]), "+f"(d[2]), "+f"(d[3])
        : "r"(a[0]), "r"(a[1]), "r"(a[2]), "r"(a[3]), "r"(b[0]), "r"(b[1]));
}
__device__ __forceinline__ uint32_t pack2h(float a, float b) {
    __half2 h = __floats2half2_rn(a, b);
    return *(uint32_t*)&h;
}

// =================== conversions ===================
__global__ void __launch_bounds__(256)
cvt_split_bias(const float* __restrict__ X, fp16* __restrict__ H,
               int n4, const float* __restrict__ bq, const float* __restrict__ bk,
               const float* __restrict__ bv, float* __restrict__ bqkv)
{
    int i = blockIdx.x * 256 + threadIdx.x;
    if (i < n4) {
        float4 v = ((const float4*)X)[i];
        uint2 hh = {pack2h(v.x, v.y), pack2h(v.z, v.w)};
        ((uint2*)H)[i] = hh;
        return;
    }
    int j = i - n4;
    if (j < DD)           bqkv[j] = bq[j];
    else if (j < 2 * DD)  bqkv[j] = bk[j - DD];
    else if (j < 3 * DD)  bqkv[j] = bv[j - 2 * DD];
}

__global__ void __launch_bounds__(256)
cvt_wT4(const float* __restrict__ Wq, const float* __restrict__ Wk,
        const float* __restrict__ Wv, const float* __restrict__ Wo,
        fp16* __restrict__ qkvTH, fp16* __restrict__ qkvTL,
        fp16* __restrict__ oTH, fp16* __restrict__ oTL)
{
    __shared__ float t[32][33];
    const int z = blockIdx.z;
    const float* W = (z == 0) ? Wq : (z == 1) ? Wk : (z == 2) ? Wv : Wo;
    fp16* TH = (z < 3) ? (qkvTH + (size_t)z * DD * DD) : oTH;
    fp16* TL = (z < 3) ? (qkvTL + (size_t)z * DD * DD) : oTL;

    const int n0 = blockIdx.x * 32, k0 = blockIdx.y * 32;
    const int tx = threadIdx.x & 31, ty = threadIdx.x >> 5;
    #pragma unroll
    for (int i = 0; i < 4; ++i)
        t[ty + 8 * i][tx] = W[(size_t)(k0 + ty + 8 * i) * DD + n0 + tx];
    __syncthreads();
    #pragma unroll
    for (int i = 0; i < 4; ++i) {
        float x = t[tx][ty + 8 * i];
        fp16 h = __float2half_rn(x);
        size_t o = (size_t)(n0 + ty + 8 * i) * DD + k0 + tx;
        TH[o] = h;
        TL[o] = __float2half_rn(x - __half2float(h));
    }
}

__global__ void __launch_bounds__(256)
cvt_wT(const float* __restrict__ W, fp16* __restrict__ TH, fp16* __restrict__ TL, int K, int N)
{
    __shared__ float t[32][33];
    const int n0 = blockIdx.x * 32, k0 = blockIdx.y * 32;
    const int tx = threadIdx.x & 31, ty = threadIdx.x >> 5;
    #pragma unroll
    for (int i = 0; i < 4; ++i)
        t[ty + 8 * i][tx] = W[(size_t)(k0 + ty + 8 * i) * N + n0 + tx];
    __syncthreads();
    #pragma unroll
    for (int i = 0; i < 4; ++i) {
        float x = t[tx][ty + 8 * i];
        fp16 h = __float2half_rn(x);
        size_t o = (size_t)(n0 + ty + 8 * i) * K + k0 + tx;
        TH[o] = h;
        TL[o] = __float2half_rn(x - __half2float(h));
    }
}

// =================== mma.sync fp16 2-term GEMM ===================
// C = A(fp16)[M,K] @ (Bh+Bl)^T ; B pre-transposed [N][K] hi/lo
// EPI: 2 = +bias,+residual (fp32 out) ; 3 = +bias -> fp16 ; 4 = +bias,relu -> fp16
#define AST 40

template<int EPI>
__global__ void __launch_bounds__(256)
gemm_mma(const fp16* __restrict__ A,
         const fp16* __restrict__ Bh, const fp16* __restrict__ Bl,
         const float* __restrict__ bias, const float* __restrict__ res,
         float* __restrict__ C, fp16* __restrict__ Ch,
         int K, int N)
{
    __shared__ fp16 sA [128 * AST];
    __shared__ fp16 sBh[128 * AST];
    __shared__ fp16 sBl[128 * AST];

    const int tid = threadIdx.x, wid = tid >> 5, lane = tid & 31;
    const int m0 = blockIdx.y * 128, n0 = blockIdx.x * 128;
    const int wm = (wid >> 2) * 64;
    const int wn = (wid & 3) * 32;

    float acc[4][4][4] = {};

    uint4 pa[2], pbh[2], pbl[2];

    const fp16* Ap  = A  + (size_t)m0 * K;
    const fp16* Bhp = Bh + (size_t)n0 * K;
    const fp16* Blp = Bl + (size_t)n0 * K;

    auto fetch = [&](int k0) {
        #pragma unroll
        for (int it = 0; it < 2; ++it) {
            int idx = tid + it * 256;
            int row = idx >> 2, g = idx & 3;
            size_t go = (size_t)row * K + k0 + g * 8;
            pa[it]  = *(const uint4*)(Ap + go);
            pbh[it] = *(const uint4*)(Bhp + go);
            pbl[it] = *(const uint4*)(Blp + go);
        }
    };
    auto stage = [&]() {
        #pragma unroll
        for (int it = 0; it < 2; ++it) {
            int idx = tid + it * 256;
            int row = idx >> 2, g = idx & 3;
            *(uint4*)&sA [row * AST + g * 8] = pa[it];
            *(uint4*)&sBh[row * AST + g * 8] = pbh[it];
            *(uint4*)&sBl[row * AST + g * 8] = pbl[it];
        }
    };

    const int a_row = wm + (lane & 15);
    const int a_kof = (lane >> 4) << 3;
    const int b_row = wn + ((lane >> 4) << 3) + (lane & 7);
    const int b_kof = ((lane >> 3) & 1) << 3;

    const uint32_t sA_b = smem_u32(sA);
    const uint32_t sBh_b = smem_u32(sBh), sBl_b = smem_u32(sBl);

    fetch(0);
    stage();
    __syncthreads();

    const int ns = K >> 5;
    for (int s = 0; s < ns; ++s) {
        if (s + 1 < ns) fetch((s + 1) << 5);

        #pragma unroll
        for (int kstep = 0; kstep < 2; ++kstep) {
            const int kk = kstep * 16;
            uint32_t af[4][4];
            #pragma unroll
            for (int mi = 0; mi < 4; ++mi) {
                uint32_t off = (uint32_t)((a_row + mi * 16) * AST + kk + a_kof) * 2;
                ldsm4(af[mi], sA_b + off);
            }
            uint32_t bfh[2][4], bfl[2][4];
            #pragma unroll
            for (int g = 0; g < 2; ++g) {
                uint32_t off = (uint32_t)((b_row + g * 16) * AST + kk + b_kof) * 2;
                ldsm4(bfh[g], sBh_b + off);
                ldsm4(bfl[g], sBl_b + off);
            }
            #pragma unroll
            for (int mi = 0; mi < 4; ++mi)
                #pragma unroll
                for (int ni = 0; ni < 4; ++ni) {
                    const uint32_t* bh_ = &bfh[ni >> 1][(ni & 1) * 2];
                    const uint32_t* bl_ = &bfl[ni >> 1][(ni & 1) * 2];
                    mma16816(acc[mi][ni], af[mi], bh_);
                    mma16816(acc[mi][ni], af[mi], bl_);
                }
        }

        __syncthreads();
        if (s + 1 < ns) {
            stage();
            __syncthreads();
        }
    }

    const int er = lane >> 2, ec = (lane & 3) * 2;
    #pragma unroll
    for (int mi = 0; mi < 4; ++mi) {
        #pragma unroll
        for (int hrow = 0; hrow < 2; ++hrow) {
            int row = m0 + wm + mi * 16 + er + hrow * 8;
            #pragma unroll
            for (int ni = 0; ni < 4; ++ni) {
                int col = n0 + wn + ni * 8 + ec;
                float v0 = acc[mi][ni][hrow * 2 + 0] + bias[col];
                float v1 = acc[mi][ni][hrow * 2 + 1] + bias[col + 1];
                if (EPI == 4) { v0 = fmaxf(v0, 0.0f); v1 = fmaxf(v1, 0.0f); }
                if (EPI == 2) {
                    v0 += res[(size_t)row * N + col];
                    v1 += res[(size_t)row * N + col + 1];
                    float2 o = {v0, v1};
                    *(float2*)(C + (size_t)row * N + col) = o;
                } else {
                    *(uint32_t*)(Ch + (size_t)row * N + col) = pack2h(v0, v1);
                }
            }
        }
    }
}

// =================== fused flash attention (q-tile 64, 128 thr) ===============
// Q, K, V all single fp16 (logits small: fp16 rounding adds ~1e-4 logit noise)
#define FST 72

__global__ void __launch_bounds__(128)
flash_kernel(const fp16* __restrict__ qkvh,
             const float* __restrict__ pos, const float* __restrict__ pmask,
             const float* __restrict__ amask, const unsigned char* __restrict__ pad,
             const float* __restrict__ table, fp16* __restrict__ ctxh)
{
    __shared__ fp16 sK[64 * FST];
    __shared__ fp16 sV[64 * FST];
    __shared__ float pxq[64], pyq[64], pmq[64];
    __shared__ float pxk[64], pyk[64], pmk[64], padk[64];

    const int q0 = blockIdx.x * 64;
    const int bh = blockIdx.y;
    const int b = bh / HH, h = bh % HH;
    const int tid = threadIdx.x, wid = tid >> 5, lane = tid & 31;
    const float* tbl = table + (size_t)h * TBL * TBL;

    const fp16* Qp = qkvh + (size_t)(b * LL) * QN + h * DKH;
    const fp16* Kp = Qp + DD;
    const fp16* Vp = Qp + 2 * DD;

    if (tid < 64) {
        int l = b * LL + q0 + tid;
        pxq[tid] = pos[2 * (size_t)l];
        pyq[tid] = pos[2 * (size_t)l + 1];
        pmq[tid] = pmask[l];
    }

    // stage Q (reuse K buffer), load Q fragments
    #pragma unroll
    for (int it = 0; it < 4; ++it) {
        int idx = tid + it * 128;
        int row = idx >> 3, g = idx & 7;
        size_t go = (size_t)(q0 + row) * QN + g * 8;
        *(uint4*)&sK[row * FST + g * 8] = *(const uint4*)(Qp + go);
    }
    __syncthreads();

    const uint32_t sK_b = smem_u32(sK), sV_b = smem_u32(sV);

    uint32_t qf[4][4];
    {
        int a_row = wid * 16 + (lane & 15);
        int a_kof = (lane >> 4) << 3;
        #pragma unroll
        for (int j = 0; j < 4; ++j) {
            uint32_t off = (uint32_t)(a_row * FST + j * 16 + a_kof) * 2;
            ldsm4(qf[j], sK_b + off);
        }
    }
    __syncthreads();

    const int er = lane >> 2, ec = (lane & 3) * 2;
    const int qr0 = q0 + wid * 16 + er;
    float mrow[2] = {-1e30f, -1e30f}, lrow[2] = {0.f, 0.f};
    float accO[8][4] = {};

    for (int kt = 0; kt < 16; ++kt) {
        const int k0 = kt * 64;
        #pragma unroll
        for (int it = 0; it < 4; ++it) {
            int idx = tid + it * 128;
            int row = idx >> 3, g = idx & 7;
            size_t go = (size_t)(k0 + row) * QN + g * 8;
            *(uint4*)&sK[row * FST + g * 8] = *(const uint4*)(Kp + go);
            *(uint4*)&sV[row * FST + g * 8] = *(const uint4*)(Vp + go);
        }
        if (tid < 64) {
            int l = b * LL + k0 + tid;
            pxk[tid] = pos[2 * (size_t)l];
            pyk[tid] = pos[2 * (size_t)l + 1];
            pmk[tid] = pmask[l];
            padk[tid] = pad[l] ? 1.f : 0.f;
        }
        __syncthreads();

        // ---- S = Q K^T ----
        float accS[8][4] = {};
        #pragma unroll
        for (int j = 0; j < 4; ++j) {
            #pragma unroll
            for (int g = 0; g < 4; ++g) {
                uint32_t kf[4];
                int b_row = g * 16 + ((lane >> 4) << 3) + (lane & 7);
                uint32_t off = (uint32_t)(b_row * FST + j * 16 + (((lane >> 3) & 1) << 3)) * 2;
                ldsm4(kf, sK_b + off);
                mma16816(accS[2 * g],     qf[j], kf);
                mma16816(accS[2 * g + 1], qf[j], kf + 2);
            }
        }

        // ---- bias + mask + online softmax ----
        float pxr[2] = {pxq[wid * 16 + er], pxq[wid * 16 + er + 8]};
        float pyr[2] = {pyq[wid * 16 + er], pyq[wid * 16 + er + 8]};
        float pmr[2] = {pmq[wid * 16 + er], pmq[wid * 16 + er + 8]};
        float newm[2] = {mrow[0], mrow[1]};
        #pragma unroll
        for (int ni = 0; ni < 8; ++ni) {
            #pragma unroll
            for (int r = 0; r < 2; ++r) {
                int kj0 = ni * 8 + ec;
                float2 am = *(const float2*)(amask + (size_t)(b * LL + qr0 + 8 * r) * LL + k0 + kj0);
                #pragma unroll
                for (int u = 0; u < 2; ++u) {
                    int kj = kj0 + u;
                    float s = accS[ni][2 * r + u] * 0.125f;
                    float ddx = fminf(fmaxf(rintf(pxr[r] - pxk[kj]), -(float)MDIST), (float)MDIST);
                    float ddy = fminf(fmaxf(rintf(pyr[r] - pyk[kj]), -(float)MDIST), (float)MDIST);
                    int dx = (int)ddx + MDIST, dy = (int)ddy + MDIST;
                    s += tbl[dy * TBL + dx] * (pmr[r] * pmk[kj]);
                    float amv = (u == 0) ? am.x : am.y;
                    if (amv == 0.f || padk[kj] != 0.f) s = -1e9f;
                    accS[ni][2 * r + u] = s;
                    newm[r] = fmaxf(newm[r], s);
                }
            }
        }
        #pragma unroll
        for (int r = 0; r < 2; ++r) {
            newm[r] = fmaxf(newm[r], __shfl_xor_sync(0xffffffffu, newm[r], 1));
            newm[r] = fmaxf(newm[r], __shfl_xor_sync(0xffffffffu, newm[r], 2));
        }
        float alpha[2], psum[2] = {0.f, 0.f};
        #pragma unroll
        for (int r = 0; r < 2; ++r) {
            alpha[r] = __expf(mrow[r] - newm[r]);
            mrow[r] = newm[r];
        }
        #pragma unroll
        for (int ni = 0; ni < 8; ++ni)
            #pragma unroll
            for (int u = 0; u < 4; ++u) {
                float p = __expf(accS[ni][u] - newm[u >> 1]);
                accS[ni][u] = p;
                psum[u >> 1] += p;
            }
        #pragma unroll
        for (int r = 0; r < 2; ++r) {
            psum[r] += __shfl_xor_sync(0xffffffffu, psum[r], 1);
            psum[r] += __shfl_xor_sync(0xffffffffu, psum[r], 2);
            lrow[r] = lrow[r] * alpha[r] + psum[r];
        }
        #pragma unroll
        for (int ni = 0; ni < 8; ++ni)
            #pragma unroll
            for (int u = 0; u < 4; ++u)
                accO[ni][u] *= alpha[u >> 1];

        // ---- O += P V ----
        #pragma unroll
        for (int j = 0; j < 4; ++j) {
            uint32_t af[4];
            af[0] = pack2h(accS[2 * j][0],     accS[2 * j][1]);
            af[1] = pack2h(accS[2 * j][2],     accS[2 * j][3]);
            af[2] = pack2h(accS[2 * j + 1][0], accS[2 * j + 1][1]);
            af[3] = pack2h(accS[2 * j + 1][2], accS[2 * j + 1][3]);
            #pragma unroll
            for (int g = 0; g < 4; ++g) {
                uint32_t vf[4];
                uint32_t off = (uint32_t)((j * 16 + (lane & 15)) * FST + g * 16 + ((lane >> 4) << 3)) * 2;
                ldsm4t(vf, sV_b + off);
                mma16816(accO[2 * g],     af, vf);
                mma16816(accO[2 * g + 1], af, vf + 2);
            }
        }
        __syncthreads();
    }

    // ---- write ctx (fp16) ----
    #pragma unroll
    for (int r = 0; r < 2; ++r) {
        float inv = 1.f / lrow[r];
        #pragma unroll
        for (int ni = 0; ni < 8; ++ni) {
            size_t o = (size_t)(b * LL + qr0 + 8 * r) * DD + h * DKH + ni * 8 + ec;
            *(uint32_t*)(ctxh + o) = pack2h(accO[ni][2 * r] * inv, accO[ni][2 * r + 1] * inv);
        }
    }
}

// ------------- LayerNorm ------------------------------------------------------
template<bool SPLIT>
__global__ void __launch_bounds__(256)
ln_kernel(const float* __restrict__ X, const float* __restrict__ g,
          const float* __restrict__ bt, float* __restrict__ O,
          fp16* __restrict__ Oh)
{
    const int row = blockIdx.x;
    const float* x = X + (size_t)row * DD;
    const int tid = threadIdx.x;

    float v[3];
    #pragma unroll
    for (int i = 0; i < 3; ++i) v[i] = x[tid + i * 256];

    __shared__ float red[256];
    float s = v[0] + v[1] + v[2];
    red[tid] = s; __syncthreads();
    for (int st = 128; st > 0; st >>= 1) {
        if (tid < st) red[tid] += red[tid + st];
        __syncthreads();
    }
    float mean = red[0] * (1.0f / DD);
    __syncthreads();

    float d0 = v[0] - mean, d1 = v[1] - mean, d2 = v[2] - mean;
    red[tid] = d0 * d0 + d1 * d1 + d2 * d2; __syncthreads();
    for (int st = 128; st > 0; st >>= 1) {
        if (tid < st) red[tid] += red[tid + st];
        __syncthreads();
    }
    float var = red[0] * (1.0f / DD);
    float inv = rsqrtf(var + 1e-5f);

    #pragma unroll
    for (int i = 0; i < 3; ++i) {
        int c = tid + i * 256;
        float o = (v[i] - mean) * inv * g[c] + bt[c];
        O[(size_t)row * DD + c] = o;
        if (SPLIT) Oh[(size_t)row * DD + c] = __float2half_rn(o);
    }
}

// ------------------------------- launch ---------------------------------------
extern "C" void kernel_launch(void* const* d_in, const int* in_sizes, int n_in,
                              void* d_out, int out_size)
{
    const float* tokens = (const float*)d_in[0];
    const float* pos    = (const float*)d_in[1];
    const float* pmask  = (const float*)d_in[2];
    const float* amask  = (const float*)d_in[3];
    const unsigned char* pad = (const unsigned char*)d_in[4];
    const float* Wq = (const float*)d_in[5];
    const float* bq = (const float*)d_in[6];
    const float* Wk = (const float*)d_in[7];
    const float* bk = (const float*)d_in[8];
    const float* Wv = (const float*)d_in[9];
    const float* bv = (const float*)d_in[10];
    const float* Wo = (const float*)d_in[11];
    const float* bo = (const float*)d_in[12];
    const float* table = (const float*)d_in[13];
    const float* W1 = (const float*)d_in[14];
    const float* b1 = (const float*)d_in[15];
    const float* W2 = (const float*)d_in[16];
    const float* b2 = (const float*)d_in[17];
    const float* ln1g = (const float*)d_in[18];
    const float* ln1b = (const float*)d_in[19];
    const float* ln2g = (const float*)d_in[20];
    const float* ln2b = (const float*)d_in[21];
    float* out = (float*)d_out;

    float *Pb, *Tb, *bqkv;
    cudaGetSymbolAddress((void**)&Pb, g_pre);
    cudaGetSymbolAddress((void**)&Tb, g_t1);
    cudaGetSymbolAddress((void**)&bqkv, g_bqkv);

    fp16 *tokh, *qkvh, *ctxh, *t1h, *ffh;
    cudaGetSymbolAddress((void**)&tokh, g_tokh);
    cudaGetSymbolAddress((void**)&qkvh, g_qkvh);
    cudaGetSymbolAddress((void**)&ctxh, g_ctxh);
    cudaGetSymbolAddress((void**)&t1h, g_t1h);
    cudaGetSymbolAddress((void**)&ffh, g_ffh);

    fp16 *wqkvh, *wqkvl, *woh, *wol, *w1h, *w1l, *w2h, *w2l;
    cudaGetSymbolAddress((void**)&wqkvh, g_wqkvh); cudaGetSymbolAddress((void**)&wqkvl, g_wqkvl);
    cudaGetSymbolAddress((void**)&woh, g_woh); cudaGetSymbolAddress((void**)&wol, g_wol);
    cudaGetSymbolAddress((void**)&w1h, g_w1h); cudaGetSymbolAddress((void**)&w1l, g_w1l);
    cudaGetSymbolAddress((void**)&w2h, g_w2h); cudaGetSymbolAddress((void**)&w2l, g_w2l);

    // prep
    cvt_wT4<<<dim3(DD / 32, DD / 32, 4), 256>>>(Wq, Wk, Wv, Wo, wqkvh, wqkvl, woh, wol);
    cvt_wT<<<dim3(FF / 32, DD / 32), 256>>>(W1, w1h, w1l, DD, FF);
    cvt_wT<<<dim3(DD / 32, FF / 32), 256>>>(W2, w2h, w2l, FF, DD);
    {
        int n4 = BL * DD / 4;
        int nblk = (n4 + QN + 255) / 256;
        cvt_split_bias<<<nblk, 256>>>(tokens, tokh, n4, bq, bk, bv, bqkv);
    }

    // fused QKV GEMM -> fp16
    gemm_mma<3><<<dim3(QN / 128, BL / 128), 256>>>(tokh, wqkvh, wqkvl, bqkv,
                                                   nullptr, nullptr, qkvh, DD, QN);

    // fused attention -> ctx fp16
    dim3 gfa(LL / 64, BB * HH);
    flash_kernel<<<gfa, 128>>>(qkvh, pos, pmask, amask, pad, table, ctxh);

    // out proj + residual -> fp32, LN1 (emits fp32 + fp16)
    gemm_mma<2><<<dim3(DD / 128, BL / 128), 256>>>(ctxh, woh, wol, bo,
                                                   tokens, Pb, nullptr, DD, DD);
    ln_kernel<true><<<BL, 256>>>(Pb, ln1g, ln1b, Tb, t1h);

    // FFN
    gemm_mma<4><<<dim3(FF / 128, BL / 128), 256>>>(t1h, w1h, w1l, b1,
                                                   nullptr, nullptr, ffh, DD, FF);
    gemm_mma<2><<<dim3(DD / 128, BL / 128), 256>>>(ffh, w2h, w2l, b2,
                                                   Tb, Pb, nullptr, FF, DD);
    ln_kernel<false><<<BL, 256>>>(Pb, ln2g, ln2b, out, nullptr);
}

// round 14
// speedup vs baseline: 2.6017x; 1.4449x over previous
#include <cuda_runtime.h>
#include <cuda_fp16.h>
#include <math.h>
#include <stdint.h>

#define BB   4
#define LL   1024
#define BL   4096
#define DD   768
#define HH   12
#define DKH  64
#define FF   3072
#define MDIST 100
#define TBL  201
#define QN   2304   // combined QKV width

typedef __half fp16;

// ---------------- scratch ----------------
__device__ float g_pre[BL * DD];
__device__ float g_t1[BL * DD];
__device__ float g_bqkv[QN];

__device__ __align__(16) fp16 g_tokh[BL * DD];
__device__ __align__(16) fp16 g_qkvh[(size_t)BL * QN];
__device__ __align__(16) fp16 g_ctxh[BL * DD];
__device__ __align__(16) fp16 g_t1h[BL * DD];
__device__ __align__(16) fp16 g_ffh[(size_t)BL * FF];

__device__ __align__(16) fp16 g_wqkvh[(size_t)QN * DD];
__device__ __align__(16) fp16 g_woh[DD * DD];
__device__ __align__(16) fp16 g_w1h[(size_t)DD * FF];
__device__ __align__(16) fp16 g_w2h[(size_t)DD * FF];

// =================== helpers ===================
__device__ __forceinline__ uint32_t smem_u32(const void* p) {
    uint32_t a;
    asm("{ .reg .u64 t; cvta.to.shared.u64 t, %1; cvt.u32.u64 %0, t; }" : "=r"(a) : "l"(p));
    return a;
}
__device__ __forceinline__ void ldsm4(uint32_t* r, uint32_t addr) {
    asm volatile("ldmatrix.sync.aligned.m8n8.x4.shared.b16 {%0,%1,%2,%3}, [%4];"
        : "=r"(r[0]), "=r"(r[1]), "=r"(r[2]), "=r"(r[3]) : "r"(addr));
}
__device__ __forceinline__ void ldsm4t(uint32_t* r, uint32_t addr) {
    asm volatile("ldmatrix.sync.aligned.m8n8.x4.trans.shared.b16 {%0,%1,%2,%3}, [%4];"
        : "=r"(r[0]), "=r"(r[1]), "=r"(r[2]), "=r"(r[3]) : "r"(addr));
}
__device__ __forceinline__ void mma16816(float* d, const uint32_t* a, const uint32_t* b) {
    asm volatile("mma.sync.aligned.m16n8k16.row.col.f32.f16.f16.f32 "
        "{%0,%1,%2,%3}, {%4,%5,%6,%7}, {%8,%9}, {%0,%1,%2,%3};"
        : "+f"(d[0]), "+f"(d[1]), "+f"(d[2]), "+f"(d[3])
        : "r"(a[0]), "r"(a[1]), "r"(a[2]), "r"(a[3]), "r"(b[0]), "r"(b[1]));
}
__device__ __forceinline__ uint32_t pack2h(float a, float b) {
    __half2 h = __floats2half2_rn(a, b);
    return *(uint32_t*)&h;
}

// =================== conversions ===================
__global__ void __launch_bounds__(256)
cvt_split_bias(const float* __restrict__ X, fp16* __restrict__ H,
               int n4, const float* __restrict__ bq, const float* __restrict__ bk,
               const float* __restrict__ bv, float* __restrict__ bqkv)
{
    int i = blockIdx.x * 256 + threadIdx.x;
    if (i < n4) {
        float4 v = ((const float4*)X)[i];
        uint2 hh = {pack2h(v.x, v.y), pack2h(v.z, v.w)};
        ((uint2*)H)[i] = hh;
        return;
    }
    int j = i - n4;
    if (j < DD)           bqkv[j] = bq[j];
    else if (j < 2 * DD)  bqkv[j] = bk[j - DD];
    else if (j < 3 * DD)  bqkv[j] = bv[j - 2 * DD];
}

__global__ void __launch_bounds__(256)
cvt_wT4(const float* __restrict__ Wq, const float* __restrict__ Wk,
        const float* __restrict__ Wv, const float* __restrict__ Wo,
        fp16* __restrict__ qkvTH, fp16* __restrict__ oTH)
{
    __shared__ float t[32][33];
    const int z = blockIdx.z;
    const float* W = (z == 0) ? Wq : (z == 1) ? Wk : (z == 2) ? Wv : Wo;
    fp16* TH = (z < 3) ? (qkvTH + (size_t)z * DD * DD) : oTH;

    const int n0 = blockIdx.x * 32, k0 = blockIdx.y * 32;
    const int tx = threadIdx.x & 31, ty = threadIdx.x >> 5;
    #pragma unroll
    for (int i = 0; i < 4; ++i)
        t[ty + 8 * i][tx] = W[(size_t)(k0 + ty + 8 * i) * DD + n0 + tx];
    __syncthreads();
    #pragma unroll
    for (int i = 0; i < 4; ++i) {
        float x = t[tx][ty + 8 * i];
        TH[(size_t)(n0 + ty + 8 * i) * DD + k0 + tx] = __float2half_rn(x);
    }
}

__global__ void __launch_bounds__(256)
cvt_wT(const float* __restrict__ W, fp16* __restrict__ TH, int K, int N)
{
    __shared__ float t[32][33];
    const int n0 = blockIdx.x * 32, k0 = blockIdx.y * 32;
    const int tx = threadIdx.x & 31, ty = threadIdx.x >> 5;
    #pragma unroll
    for (int i = 0; i < 4; ++i)
        t[ty + 8 * i][tx] = W[(size_t)(k0 + ty + 8 * i) * N + n0 + tx];
    __syncthreads();
    #pragma unroll
    for (int i = 0; i < 4; ++i) {
        float x = t[tx][ty + 8 * i];
        TH[(size_t)(n0 + ty + 8 * i) * K + k0 + tx] = __float2half_rn(x);
    }
}

// =================== mma.sync fp16 GEMM (single-term weights) =================
// C = A(fp16)[M,K] @ B^T ; B pre-transposed [N][K]
// EPI: 2 = +bias,+residual (fp32 out) ; 3 = +bias -> fp16 ; 4 = +bias,relu -> fp16
#define AST 40

template<int EPI>
__global__ void __launch_bounds__(256)
gemm_mma(const fp16* __restrict__ A, const fp16* __restrict__ Bh,
         const float* __restrict__ bias, const float* __restrict__ res,
         float* __restrict__ C, fp16* __restrict__ Ch,
         int K, int N)
{
    __shared__ fp16 sA[128 * AST];
    __shared__ fp16 sB[128 * AST];

    const int tid = threadIdx.x, wid = tid >> 5, lane = tid & 31;
    const int m0 = blockIdx.y * 128, n0 = blockIdx.x * 128;
    const int wm = (wid >> 2) * 64;
    const int wn = (wid & 3) * 32;

    float acc[4][4][4] = {};

    uint4 pa[2], pb[2];

    const fp16* Ap = A  + (size_t)m0 * K;
    const fp16* Bp = Bh + (size_t)n0 * K;

    auto fetch = [&](int k0) {
        #pragma unroll
        for (int it = 0; it < 2; ++it) {
            int idx = tid + it * 256;
            int row = idx >> 2, g = idx & 3;
            size_t go = (size_t)row * K + k0 + g * 8;
            pa[it] = *(const uint4*)(Ap + go);
            pb[it] = *(const uint4*)(Bp + go);
        }
    };
    auto stage = [&]() {
        #pragma unroll
        for (int it = 0; it < 2; ++it) {
            int idx = tid + it * 256;
            int row = idx >> 2, g = idx & 3;
            *(uint4*)&sA[row * AST + g * 8] = pa[it];
            *(uint4*)&sB[row * AST + g * 8] = pb[it];
        }
    };

    const int a_row = wm + (lane & 15);
    const int a_kof = (lane >> 4) << 3;
    const int b_row = wn + ((lane >> 4) << 3) + (lane & 7);
    const int b_kof = ((lane >> 3) & 1) << 3;

    const uint32_t sA_b = smem_u32(sA), sB_b = smem_u32(sB);

    fetch(0);
    stage();
    __syncthreads();

    const int ns = K >> 5;
    for (int s = 0; s < ns; ++s) {
        if (s + 1 < ns) fetch((s + 1) << 5);

        #pragma unroll
        for (int kstep = 0; kstep < 2; ++kstep) {
            const int kk = kstep * 16;
            uint32_t af[4][4];
            #pragma unroll
            for (int mi = 0; mi < 4; ++mi) {
                uint32_t off = (uint32_t)((a_row + mi * 16) * AST + kk + a_kof) * 2;
                ldsm4(af[mi], sA_b + off);
            }
            uint32_t bf[2][4];
            #pragma unroll
            for (int g = 0; g < 2; ++g) {
                uint32_t off = (uint32_t)((b_row + g * 16) * AST + kk + b_kof) * 2;
                ldsm4(bf[g], sB_b + off);
            }
            #pragma unroll
            for (int mi = 0; mi < 4; ++mi)
                #pragma unroll
                for (int ni = 0; ni < 4; ++ni)
                    mma16816(acc[mi][ni], af[mi], &bf[ni >> 1][(ni & 1) * 2]);
        }

        __syncthreads();
        if (s + 1 < ns) {
            stage();
            __syncthreads();
        }
    }

    const int er = lane >> 2, ec = (lane & 3) * 2;
    #pragma unroll
    for (int mi = 0; mi < 4; ++mi) {
        #pragma unroll
        for (int hrow = 0; hrow < 2; ++hrow) {
            int row = m0 + wm + mi * 16 + er + hrow * 8;
            #pragma unroll
            for (int ni = 0; ni < 4; ++ni) {
                int col = n0 + wn + ni * 8 + ec;
                float v0 = acc[mi][ni][hrow * 2 + 0] + bias[col];
                float v1 = acc[mi][ni][hrow * 2 + 1] + bias[col + 1];
                if (EPI == 4) { v0 = fmaxf(v0, 0.0f); v1 = fmaxf(v1, 0.0f); }
                if (EPI == 2) {
                    v0 += res[(size_t)row * N + col];
                    v1 += res[(size_t)row * N + col + 1];
                    float2 o = {v0, v1};
                    *(float2*)(C + (size_t)row * N + col) = o;
                } else {
                    *(uint32_t*)(Ch + (size_t)row * N + col) = pack2h(v0, v1);
                }
            }
        }
    }
}

// =================== fused flash attention (q-tile 64, 128 thr) ===============
#define FST 72

__global__ void __launch_bounds__(128)
flash_kernel(const fp16* __restrict__ qkvh,
             const float* __restrict__ pos, const float* __restrict__ pmask,
             const float* __restrict__ amask, const unsigned char* __restrict__ pad,
             const float* __restrict__ table, fp16* __restrict__ ctxh)
{
    __shared__ fp16 sK[64 * FST];
    __shared__ fp16 sV[64 * FST];
    __shared__ float pxq[64], pyq[64], pmq[64];
    __shared__ float pxk[64], pyk[64], pmk[64], padk[64];

    const int q0 = blockIdx.x * 64;
    const int bh = blockIdx.y;
    const int b = bh / HH, h = bh % HH;
    const int tid = threadIdx.x, wid = tid >> 5, lane = tid & 31;
    const float* tbl = table + (size_t)h * TBL * TBL;

    const fp16* Qp = qkvh + (size_t)(b * LL) * QN + h * DKH;
    const fp16* Kp = Qp + DD;
    const fp16* Vp = Qp + 2 * DD;

    if (tid < 64) {
        int l = b * LL + q0 + tid;
        pxq[tid] = pos[2 * (size_t)l];
        pyq[tid] = pos[2 * (size_t)l + 1];
        pmq[tid] = pmask[l];
    }

    #pragma unroll
    for (int it = 0; it < 4; ++it) {
        int idx = tid + it * 128;
        int row = idx >> 3, g = idx & 7;
        size_t go = (size_t)(q0 + row) * QN + g * 8;
        *(uint4*)&sK[row * FST + g * 8] = *(const uint4*)(Qp + go);
    }
    __syncthreads();

    const uint32_t sK_b = smem_u32(sK), sV_b = smem_u32(sV);

    uint32_t qf[4][4];
    {
        int a_row = wid * 16 + (lane & 15);
        int a_kof = (lane >> 4) << 3;
        #pragma unroll
        for (int j = 0; j < 4; ++j) {
            uint32_t off = (uint32_t)(a_row * FST + j * 16 + a_kof) * 2;
            ldsm4(qf[j], sK_b + off);
        }
    }
    __syncthreads();

    const int er = lane >> 2, ec = (lane & 3) * 2;
    const int qr0 = q0 + wid * 16 + er;
    float mrow[2] = {-1e30f, -1e30f}, lrow[2] = {0.f, 0.f};
    float accO[8][4] = {};

    for (int kt = 0; kt < 16; ++kt) {
        const int k0 = kt * 64;
        #pragma unroll
        for (int it = 0; it < 4; ++it) {
            int idx = tid + it * 128;
            int row = idx >> 3, g = idx & 7;
            size_t go = (size_t)(k0 + row) * QN + g * 8;
            *(uint4*)&sK[row * FST + g * 8] = *(const uint4*)(Kp + go);
            *(uint4*)&sV[row * FST + g * 8] = *(const uint4*)(Vp + go);
        }
        if (tid < 64) {
            int l = b * LL + k0 + tid;
            pxk[tid] = pos[2 * (size_t)l];
            pyk[tid] = pos[2 * (size_t)l + 1];
            pmk[tid] = pmask[l];
            padk[tid] = pad[l] ? 1.f : 0.f;
        }
        __syncthreads();

        // ---- S = Q K^T ----
        float accS[8][4] = {};
        #pragma unroll
        for (int j = 0; j < 4; ++j) {
            #pragma unroll
            for (int g = 0; g < 4; ++g) {
                uint32_t kf[4];
                int b_row = g * 16 + ((lane >> 4) << 3) + (lane & 7);
                uint32_t off = (uint32_t)(b_row * FST + j * 16 + (((lane >> 3) & 1) << 3)) * 2;
                ldsm4(kf, sK_b + off);
                mma16816(accS[2 * g],     qf[j], kf);
                mma16816(accS[2 * g + 1], qf[j], kf + 2);
            }
        }

        // ---- bias + mask + online softmax ----
        float pxr[2] = {pxq[wid * 16 + er], pxq[wid * 16 + er + 8]};
        float pyr[2] = {pyq[wid * 16 + er], pyq[wid * 16 + er + 8]};
        float pmr[2] = {pmq[wid * 16 + er], pmq[wid * 16 + er + 8]};
        float newm[2] = {mrow[0], mrow[1]};
        #pragma unroll
        for (int ni = 0; ni < 8; ++ni) {
            #pragma unroll
            for (int r = 0; r < 2; ++r) {
                int kj0 = ni * 8 + ec;
                float2 am = *(const float2*)(amask + (size_t)(b * LL + qr0 + 8 * r) * LL + k0 + kj0);
                #pragma unroll
                for (int u = 0; u < 2; ++u) {
                    int kj = kj0 + u;
                    float s = accS[ni][2 * r + u] * 0.125f;
                    float ddx = fminf(fmaxf(rintf(pxr[r] - pxk[kj]), -(float)MDIST), (float)MDIST);
                    float ddy = fminf(fmaxf(rintf(pyr[r] - pyk[kj]), -(float)MDIST), (float)MDIST);
                    int dx = (int)ddx + MDIST, dy = (int)ddy + MDIST;
                    s += tbl[dy * TBL + dx] * (pmr[r] * pmk[kj]);
                    float amv = (u == 0) ? am.x : am.y;
                    if (amv == 0.f || padk[kj] != 0.f) s = -1e9f;
                    accS[ni][2 * r + u] = s;
                    newm[r] = fmaxf(newm[r], s);
                }
            }
        }
        #pragma unroll
        for (int r = 0; r < 2; ++r) {
            newm[r] = fmaxf(newm[r], __shfl_xor_sync(0xffffffffu, newm[r], 1));
            newm[r] = fmaxf(newm[r], __shfl_xor_sync(0xffffffffu, newm[r], 2));
        }
        float alpha[2], psum[2] = {0.f, 0.f};
        #pragma unroll
        for (int r = 0; r < 2; ++r) {
            alpha[r] = __expf(mrow[r] - newm[r]);
            mrow[r] = newm[r];
        }
        #pragma unroll
        for (int ni = 0; ni < 8; ++ni)
            #pragma unroll
            for (int u = 0; u < 4; ++u) {
                float p = __expf(accS[ni][u] - newm[u >> 1]);
                accS[ni][u] = p;
                psum[u >> 1] += p;
            }
        #pragma unroll
        for (int r = 0; r < 2; ++r) {
            psum[r] += __shfl_xor_sync(0xffffffffu, psum[r], 1);
            psum[r] += __shfl_xor_sync(0xffffffffu, psum[r], 2);
            lrow[r] = lrow[r] * alpha[r] + psum[r];
        }
        #pragma unroll
        for (int ni = 0; ni < 8; ++ni)
            #pragma unroll
            for (int u = 0; u < 4; ++u)
                accO[ni][u] *= alpha[u >> 1];

        // ---- O += P V ----
        #pragma unroll
        for (int j = 0; j < 4; ++j) {
            uint32_t af[4];
            af[0] = pack2h(accS[2 * j][0],     accS[2 * j][1]);
            af[1] = pack2h(accS[2 * j][2],     accS[2 * j][3]);
            af[2] = pack2h(accS[2 * j + 1][0], accS[2 * j + 1][1]);
            af[3] = pack2h(accS[2 * j + 1][2], accS[2 * j + 1][3]);
            #pragma unroll
            for (int g = 0; g < 4; ++g) {
                uint32_t vf[4];
                uint32_t off = (uint32_t)((j * 16 + (lane & 15)) * FST + g * 16 + ((lane >> 4) << 3)) * 2;
                ldsm4t(vf, sV_b + off);
                mma16816(accO[2 * g],     af, vf);
                mma16816(accO[2 * g + 1], af, vf + 2);
            }
        }
        __syncthreads();
    }

    #pragma unroll
    for (int r = 0; r < 2; ++r) {
        float inv = 1.f / lrow[r];
        #pragma unroll
        for (int ni = 0; ni < 8; ++ni) {
            size_t o = (size_t)(b * LL + qr0 + 8 * r) * DD + h * DKH + ni * 8 + ec;
            *(uint32_t*)(ctxh + o) = pack2h(accO[ni][2 * r] * inv, accO[ni][2 * r + 1] * inv);
        }
    }
}

// ------------- LayerNorm ------------------------------------------------------
template<bool SPLIT>
__global__ void __launch_bounds__(256)
ln_kernel(const float* __restrict__ X, const float* __restrict__ g,
          const float* __restrict__ bt, float* __restrict__ O,
          fp16* __restrict__ Oh)
{
    const int row = blockIdx.x;
    const float* x = X + (size_t)row * DD;
    const int tid = threadIdx.x;

    float v[3];
    #pragma unroll
    for (int i = 0; i < 3; ++i) v[i] = x[tid + i * 256];

    __shared__ float red[256];
    float s = v[0] + v[1] + v[2];
    red[tid] = s; __syncthreads();
    for (int st = 128; st > 0; st >>= 1) {
        if (tid < st) red[tid] += red[tid + st];
        __syncthreads();
    }
    float mean = red[0] * (1.0f / DD);
    __syncthreads();

    float d0 = v[0] - mean, d1 = v[1] - mean, d2 = v[2] - mean;
    red[tid] = d0 * d0 + d1 * d1 + d2 * d2; __syncthreads();
    for (int st = 128; st > 0; st >>= 1) {
        if (tid < st) red[tid] += red[tid + st];
        __syncthreads();
    }
    float var = red[0] * (1.0f / DD);
    float inv = rsqrtf(var + 1e-5f);

    #pragma unroll
    for (int i = 0; i < 3; ++i) {
        int c = tid + i * 256;
        float o = (v[i] - mean) * inv * g[c] + bt[c];
        O[(size_t)row * DD + c] = o;
        if (SPLIT) Oh[(size_t)row * DD + c] = __float2half_rn(o);
    }
}

// ------------------------------- launch ---------------------------------------
extern "C" void kernel_launch(void* const* d_in, const int* in_sizes, int n_in,
                              void* d_out, int out_size)
{
    const float* tokens = (const float*)d_in[0];
    const float* pos    = (const float*)d_in[1];
    const float* pmask  = (const float*)d_in[2];
    const float* amask  = (const float*)d_in[3];
    const unsigned char* pad = (const unsigned char*)d_in[4];
    const float* Wq = (const float*)d_in[5];
    const float* bq = (const float*)d_in[6];
    const float* Wk = (const float*)d_in[7];
    const float* bk = (const float*)d_in[8];
    const float* Wv = (const float*)d_in[9];
    const float* bv = (const float*)d_in[10];
    const float* Wo = (const float*)d_in[11];
    const float* bo = (const float*)d_in[12];
    const float* table = (const float*)d_in[13];
    const float* W1 = (const float*)d_in[14];
    const float* b1 = (const float*)d_in[15];
    const float* W2 = (const float*)d_in[16];
    const float* b2 = (const float*)d_in[17];
    const float* ln1g = (const float*)d_in[18];
    const float* ln1b = (const float*)d_in[19];
    const float* ln2g = (const float*)d_in[20];
    const float* ln2b = (const float*)d_in[21];
    float* out = (float*)d_out;

    float *Pb, *Tb, *bqkv;
    cudaGetSymbolAddress((void**)&Pb, g_pre);
    cudaGetSymbolAddress((void**)&Tb, g_t1);
    cudaGetSymbolAddress((void**)&bqkv, g_bqkv);

    fp16 *tokh, *qkvh, *ctxh, *t1h, *ffh;
    cudaGetSymbolAddress((void**)&tokh, g_tokh);
    cudaGetSymbolAddress((void**)&qkvh, g_qkvh);
    cudaGetSymbolAddress((void**)&ctxh, g_ctxh);
    cudaGetSymbolAddress((void**)&t1h, g_t1h);
    cudaGetSymbolAddress((void**)&ffh, g_ffh);

    fp16 *wqkvh, *woh, *w1h, *w2h;
    cudaGetSymbolAddress((void**)&wqkvh, g_wqkvh);
    cudaGetSymbolAddress((void**)&woh, g_woh);
    cudaGetSymbolAddress((void**)&w1h, g_w1h);
    cudaGetSymbolAddress((void**)&w2h, g_w2h);

    // prep
    cvt_wT4<<<dim3(DD / 32, DD / 32, 4), 256>>>(Wq, Wk, Wv, Wo, wqkvh, woh);
    cvt_wT<<<dim3(FF / 32, DD / 32), 256>>>(W1, w1h, DD, FF);
    cvt_wT<<<dim3(DD / 32, FF / 32), 256>>>(W2, w2h, FF, DD);
    {
        int n4 = BL * DD / 4;
        int nblk = (n4 + QN + 255) / 256;
        cvt_split_bias<<<nblk, 256>>>(tokens, tokh, n4, bq, bk, bv, bqkv);
    }

    // fused QKV GEMM -> fp16
    gemm_mma<3><<<dim3(QN / 128, BL / 128), 256>>>(tokh, wqkvh, bqkv,
                                                   nullptr, nullptr, qkvh, DD, QN);

    // fused attention -> ctx fp16
    dim3 gfa(LL / 64, BB * HH);
    flash_kernel<<<gfa, 128>>>(qkvh, pos, pmask, amask, pad, table, ctxh);

    // out proj + residual -> fp32, LN1 (emits fp32 + fp16)
    gemm_mma<2><<<dim3(DD / 128, BL / 128), 256>>>(ctxh, woh, bo,
                                                   tokens, Pb, nullptr, DD, DD);
    ln_kernel<true><<<BL, 256>>>(Pb, ln1g, ln1b, Tb, t1h);

    // FFN
    gemm_mma<4><<<dim3(FF / 128, BL / 128), 256>>>(t1h, w1h, b1,
                                                   nullptr, nullptr, ffh, DD, FF);
    gemm_mma<2><<<dim3(DD / 128, BL / 128), 256>>>(ffh, w2h, b2,
                                                   Tb, Pb, nullptr, FF, DD);
    ln_kernel<false><<<BL, 256>>>(Pb, ln2g, ln2b, out, nullptr);
}

// round 15
// speedup vs baseline: 2.6410x; 1.0151x over previous
#include <cuda_runtime.h>
#include <cuda_fp16.h>
#include <math.h>
#include <stdint.h>

#define BB   4
#define LL   1024
#define BL   4096
#define DD   768
#define HH   12
#define DKH  64
#define FF   3072
#define MDIST 100
#define TBL  201
#define QN   2304   // combined QKV width

typedef __half fp16;

// ---------------- scratch ----------------
__device__ float g_pre[BL * DD];
__device__ float g_t1[BL * DD];
__device__ float g_bqkv[QN];

__device__ __align__(16) uint16_t g_idx[(size_t)BB * LL * LL];  // relpos idx / 0xFFFF mask

__device__ __align__(16) fp16 g_tokh[BL * DD];
__device__ __align__(16) fp16 g_qkvh[(size_t)BL * QN];
__device__ __align__(16) fp16 g_ctxh[BL * DD];
__device__ __align__(16) fp16 g_t1h[BL * DD];
__device__ __align__(16) fp16 g_ffh[(size_t)BL * FF];

__device__ __align__(16) fp16 g_wqkvh[(size_t)QN * DD];
__device__ __align__(16) fp16 g_woh[DD * DD];
__device__ __align__(16) fp16 g_w1h[(size_t)DD * FF];
__device__ __align__(16) fp16 g_w2h[(size_t)DD * FF];

// =================== helpers ===================
__device__ __forceinline__ uint32_t smem_u32(const void* p) {
    uint32_t a;
    asm("{ .reg .u64 t; cvta.to.shared.u64 t, %1; cvt.u32.u64 %0, t; }" : "=r"(a) : "l"(p));
    return a;
}
__device__ __forceinline__ void ldsm4(uint32_t* r, uint32_t addr) {
    asm volatile("ldmatrix.sync.aligned.m8n8.x4.shared.b16 {%0,%1,%2,%3}, [%4];"
        : "=r"(r[0]), "=r"(r[1]), "=r"(r[2]), "=r"(r[3]) : "r"(addr));
}
__device__ __forceinline__ void ldsm4t(uint32_t* r, uint32_t addr) {
    asm volatile("ldmatrix.sync.aligned.m8n8.x4.trans.shared.b16 {%0,%1,%2,%3}, [%4];"
        : "=r"(r[0]), "=r"(r[1]), "=r"(r[2]), "=r"(r[3]) : "r"(addr));
}
__device__ __forceinline__ void mma16816(float* d, const uint32_t* a, const uint32_t* b) {
    asm volatile("mma.sync.aligned.m16n8k16.row.col.f32.f16.f16.f32 "
        "{%0,%1,%2,%3}, {%4,%5,%6,%7}, {%8,%9}, {%0,%1,%2,%3};"
        : "+f"(d[0]), "+f"(d[1]), "+f"(d[2]), "+f"(d[3])
        : "r"(a[0]), "r"(a[1]), "r"(a[2]), "r"(a[3]), "r"(b[0]), "r"(b[1]));
}
__device__ __forceinline__ uint32_t pack2h(float a, float b) {
    __half2 h = __floats2half2_rn(a, b);
    return *(uint32_t*)&h;
}

// =================== conversions ===================
__global__ void __launch_bounds__(256)
cvt_split_bias(const float* __restrict__ X, fp16* __restrict__ H,
               int n4, const float* __restrict__ bq, const float* __restrict__ bk,
               const float* __restrict__ bv, float* __restrict__ bqkv)
{
    int i = blockIdx.x * 256 + threadIdx.x;
    if (i < n4) {
        float4 v = ((const float4*)X)[i];
        uint2 hh = {pack2h(v.x, v.y), pack2h(v.z, v.w)};
        ((uint2*)H)[i] = hh;
        return;
    }
    int j = i - n4;
    if (j < DD)           bqkv[j] = bq[j];
    else if (j < 2 * DD)  bqkv[j] = bk[j - DD];
    else if (j < 3 * DD)  bqkv[j] = bv[j - 2 * DD];
}

// precompute relpos index + mask sentinel: one thread = 4 consecutive k
__global__ void __launch_bounds__(256)
idx_kernel(const float* __restrict__ pos, const float* __restrict__ amask,
           const unsigned char* __restrict__ pad, uint16_t* __restrict__ idx)
{
    size_t t = (size_t)blockIdx.x * 256 + threadIdx.x;   // over B*L*L/4
    size_t e0 = t * 4;
    int b = (int)(e0 >> 20);
    int r = (int)(e0 & (LL * (size_t)LL - 1));
    int q = r >> 10, k0 = r & 1023;

    float pxq = pos[2 * (size_t)(b * LL + q)];
    float pyq = pos[2 * (size_t)(b * LL + q) + 1];
    float4 am = *(const float4*)(amask + e0);
    float amv[4] = {am.x, am.y, am.z, am.w};

    uint16_t o[4];
    #pragma unroll
    for (int u = 0; u < 4; ++u) {
        int k = k0 + u;
        float pxk = pos[2 * (size_t)(b * LL + k)];
        float pyk = pos[2 * (size_t)(b * LL + k) + 1];
        float ddx = fminf(fmaxf(rintf(pxq - pxk), -(float)MDIST), (float)MDIST);
        float ddy = fminf(fmaxf(rintf(pyq - pyk), -(float)MDIST), (float)MDIST);
        int dx = (int)ddx + MDIST, dy = (int)ddy + MDIST;
        bool masked = (amv[u] == 0.0f) || (pad[b * LL + k] != 0);
        o[u] = masked ? 0xFFFFu : (uint16_t)(dy * TBL + dx);
    }
    *(uint2*)(idx + e0) = *(uint2*)o;
}

__global__ void __launch_bounds__(256)
cvt_wT4(const float* __restrict__ Wq, const float* __restrict__ Wk,
        const float* __restrict__ Wv, const float* __restrict__ Wo,
        fp16* __restrict__ qkvTH, fp16* __restrict__ oTH)
{
    __shared__ float t[32][33];
    const int z = blockIdx.z;
    const float* W = (z == 0) ? Wq : (z == 1) ? Wk : (z == 2) ? Wv : Wo;
    fp16* TH = (z < 3) ? (qkvTH + (size_t)z * DD * DD) : oTH;

    const int n0 = blockIdx.x * 32, k0 = blockIdx.y * 32;
    const int tx = threadIdx.x & 31, ty = threadIdx.x >> 5;
    #pragma unroll
    for (int i = 0; i < 4; ++i)
        t[ty + 8 * i][tx] = W[(size_t)(k0 + ty + 8 * i) * DD + n0 + tx];
    __syncthreads();
    #pragma unroll
    for (int i = 0; i < 4; ++i) {
        float x = t[tx][ty + 8 * i];
        TH[(size_t)(n0 + ty + 8 * i) * DD + k0 + tx] = __float2half_rn(x);
    }
}

__global__ void __launch_bounds__(256)
cvt_wT(const float* __restrict__ W, fp16* __restrict__ TH, int K, int N)
{
    __shared__ float t[32][33];
    const int n0 = blockIdx.x * 32, k0 = blockIdx.y * 32;
    const int tx = threadIdx.x & 31, ty = threadIdx.x >> 5;
    #pragma unroll
    for (int i = 0; i < 4; ++i)
        t[ty + 8 * i][tx] = W[(size_t)(k0 + ty + 8 * i) * N + n0 + tx];
    __syncthreads();
    #pragma unroll
    for (int i = 0; i < 4; ++i) {
        float x = t[tx][ty + 8 * i];
        TH[(size_t)(n0 + ty + 8 * i) * K + k0 + tx] = __float2half_rn(x);
    }
}

// =================== mma.sync fp16 GEMM (single-term weights) =================
#define AST 40

template<int EPI>
__global__ void __launch_bounds__(256)
gemm_mma(const fp16* __restrict__ A, const fp16* __restrict__ Bh,
         const float* __restrict__ bias, const float* __restrict__ res,
         float* __restrict__ C, fp16* __restrict__ Ch,
         int K, int N)
{
    __shared__ fp16 sA[128 * AST];
    __shared__ fp16 sB[128 * AST];

    const int tid = threadIdx.x, wid = tid >> 5, lane = tid & 31;
    const int m0 = blockIdx.y * 128, n0 = blockIdx.x * 128;
    const int wm = (wid >> 2) * 64;
    const int wn = (wid & 3) * 32;

    float acc[4][4][4] = {};

    uint4 pa[2], pb[2];

    const fp16* Ap = A  + (size_t)m0 * K;
    const fp16* Bp = Bh + (size_t)n0 * K;

    auto fetch = [&](int k0) {
        #pragma unroll
        for (int it = 0; it < 2; ++it) {
            int idx = tid + it * 256;
            int row = idx >> 2, g = idx & 3;
            size_t go = (size_t)row * K + k0 + g * 8;
            pa[it] = *(const uint4*)(Ap + go);
            pb[it] = *(const uint4*)(Bp + go);
        }
    };
    auto stage = [&]() {
        #pragma unroll
        for (int it = 0; it < 2; ++it) {
            int idx = tid + it * 256;
            int row = idx >> 2, g = idx & 3;
            *(uint4*)&sA[row * AST + g * 8] = pa[it];
            *(uint4*)&sB[row * AST + g * 8] = pb[it];
        }
    };

    const int a_row = wm + (lane & 15);
    const int a_kof = (lane >> 4) << 3;
    const int b_row = wn + ((lane >> 4) << 3) + (lane & 7);
    const int b_kof = ((lane >> 3) & 1) << 3;

    const uint32_t sA_b = smem_u32(sA), sB_b = smem_u32(sB);

    fetch(0);
    stage();
    __syncthreads();

    const int ns = K >> 5;
    for (int s = 0; s < ns; ++s) {
        if (s + 1 < ns) fetch((s + 1) << 5);

        #pragma unroll
        for (int kstep = 0; kstep < 2; ++kstep) {
            const int kk = kstep * 16;
            uint32_t af[4][4];
            #pragma unroll
            for (int mi = 0; mi < 4; ++mi) {
                uint32_t off = (uint32_t)((a_row + mi * 16) * AST + kk + a_kof) * 2;
                ldsm4(af[mi], sA_b + off);
            }
            uint32_t bf[2][4];
            #pragma unroll
            for (int g = 0; g < 2; ++g) {
                uint32_t off = (uint32_t)((b_row + g * 16) * AST + kk + b_kof) * 2;
                ldsm4(bf[g], sB_b + off);
            }
            #pragma unroll
            for (int mi = 0; mi < 4; ++mi)
                #pragma unroll
                for (int ni = 0; ni < 4; ++ni)
                    mma16816(acc[mi][ni], af[mi], &bf[ni >> 1][(ni & 1) * 2]);
        }

        __syncthreads();
        if (s + 1 < ns) {
            stage();
            __syncthreads();
        }
    }

    const int er = lane >> 2, ec = (lane & 3) * 2;
    #pragma unroll
    for (int mi = 0; mi < 4; ++mi) {
        #pragma unroll
        for (int hrow = 0; hrow < 2; ++hrow) {
            int row = m0 + wm + mi * 16 + er + hrow * 8;
            #pragma unroll
            for (int ni = 0; ni < 4; ++ni) {
                int col = n0 + wn + ni * 8 + ec;
                float v0 = acc[mi][ni][hrow * 2 + 0] + bias[col];
                float v1 = acc[mi][ni][hrow * 2 + 1] + bias[col + 1];
                if (EPI == 4) { v0 = fmaxf(v0, 0.0f); v1 = fmaxf(v1, 0.0f); }
                if (EPI == 2) {
                    v0 += res[(size_t)row * N + col];
                    v1 += res[(size_t)row * N + col + 1];
                    float2 o = {v0, v1};
                    *(float2*)(C + (size_t)row * N + col) = o;
                } else {
                    *(uint32_t*)(Ch + (size_t)row * N + col) = pack2h(v0, v1);
                }
            }
        }
    }
}

// =================== fused flash attention (q-tile 64, 128 thr) ===============
#define FST 72

__global__ void __launch_bounds__(128)
flash_kernel(const fp16* __restrict__ qkvh, const float* __restrict__ pmask,
             const uint16_t* __restrict__ idx,
             const float* __restrict__ table, fp16* __restrict__ ctxh)
{
    __shared__ fp16 sK[64 * FST];
    __shared__ fp16 sV[64 * FST];
    __shared__ float pmq[64], pmk[64];

    const int q0 = blockIdx.x * 64;
    const int bh = blockIdx.y;
    const int b = bh / HH, h = bh % HH;
    const int tid = threadIdx.x, wid = tid >> 5, lane = tid & 31;
    const float* tbl = table + (size_t)h * TBL * TBL;

    const fp16* Qp = qkvh + (size_t)(b * LL) * QN + h * DKH;
    const fp16* Kp = Qp + DD;
    const fp16* Vp = Qp + 2 * DD;

    if (tid < 64) pmq[tid] = pmask[b * LL + q0 + tid];

    #pragma unroll
    for (int it = 0; it < 4; ++it) {
        int i2 = tid + it * 128;
        int row = i2 >> 3, g = i2 & 7;
        size_t go = (size_t)(q0 + row) * QN + g * 8;
        *(uint4*)&sK[row * FST + g * 8] = *(const uint4*)(Qp + go);
    }
    __syncthreads();

    const uint32_t sK_b = smem_u32(sK), sV_b = smem_u32(sV);

    uint32_t qf[4][4];
    {
        int a_row = wid * 16 + (lane & 15);
        int a_kof = (lane >> 4) << 3;
        #pragma unroll
        for (int j = 0; j < 4; ++j) {
            uint32_t off = (uint32_t)(a_row * FST + j * 16 + a_kof) * 2;
            ldsm4(qf[j], sK_b + off);
        }
    }
    __syncthreads();

    const int er = lane >> 2, ec = (lane & 3) * 2;
    const int qr0 = q0 + wid * 16 + er;
    const uint16_t* idx0 = idx + ((size_t)b << 20) + (size_t)qr0 * LL;
    float mrow[2] = {-1e30f, -1e30f}, lrow[2] = {0.f, 0.f};
    float accO[8][4] = {};

    for (int kt = 0; kt < 16; ++kt) {
        const int k0 = kt * 64;
        #pragma unroll
        for (int it = 0; it < 4; ++it) {
            int i2 = tid + it * 128;
            int row = i2 >> 3, g = i2 & 7;
            size_t go = (size_t)(k0 + row) * QN + g * 8;
            *(uint4*)&sK[row * FST + g * 8] = *(const uint4*)(Kp + go);
            *(uint4*)&sV[row * FST + g * 8] = *(const uint4*)(Vp + go);
        }
        if (tid < 64) pmk[tid] = pmask[b * LL + k0 + tid];
        __syncthreads();

        // ---- S = Q K^T ----
        float accS[8][4] = {};
        #pragma unroll
        for (int j = 0; j < 4; ++j) {
            #pragma unroll
            for (int g = 0; g < 4; ++g) {
                uint32_t kf[4];
                int b_row = g * 16 + ((lane >> 4) << 3) + (lane & 7);
                uint32_t off = (uint32_t)(b_row * FST + j * 16 + (((lane >> 3) & 1) << 3)) * 2;
                ldsm4(kf, sK_b + off);
                mma16816(accS[2 * g],     qf[j], kf);
                mma16816(accS[2 * g + 1], qf[j], kf + 2);
            }
        }

        // ---- bias (precomputed idx) + online softmax ----
        float pmr[2] = {pmq[wid * 16 + er], pmq[wid * 16 + er + 8]};
        float newm[2] = {mrow[0], mrow[1]};
        #pragma unroll
        for (int ni = 0; ni < 8; ++ni) {
            #pragma unroll
            for (int r = 0; r < 2; ++r) {
                int kj0 = ni * 8 + ec;
                uint32_t ii = *(const uint32_t*)(idx0 + (size_t)(8 * r) * LL + k0 + kj0);
                uint32_t i0 = ii & 0xFFFFu, i1 = ii >> 16;
                float s0 = accS[ni][2 * r + 0] * 0.125f;
                float s1 = accS[ni][2 * r + 1] * 0.125f;
                s0 = (i0 == 0xFFFFu) ? -1e9f : s0 + tbl[i0] * (pmr[r] * pmk[kj0]);
                s1 = (i1 == 0xFFFFu) ? -1e9f : s1 + tbl[i1] * (pmr[r] * pmk[kj0 + 1]);
                accS[ni][2 * r + 0] = s0;
                accS[ni][2 * r + 1] = s1;
                newm[r] = fmaxf(newm[r], fmaxf(s0, s1));
            }
        }
        #pragma unroll
        for (int r = 0; r < 2; ++r) {
            newm[r] = fmaxf(newm[r], __shfl_xor_sync(0xffffffffu, newm[r], 1));
            newm[r] = fmaxf(newm[r], __shfl_xor_sync(0xffffffffu, newm[r], 2));
        }
        float alpha[2], psum[2] = {0.f, 0.f};
        #pragma unroll
        for (int r = 0; r < 2; ++r) {
            alpha[r] = __expf(mrow[r] - newm[r]);
            mrow[r] = newm[r];
        }
        #pragma unroll
        for (int ni = 0; ni < 8; ++ni)
            #pragma unroll
            for (int u = 0; u < 4; ++u) {
                float p = __expf(accS[ni][u] - newm[u >> 1]);
                accS[ni][u] = p;
                psum[u >> 1] += p;
            }
        #pragma unroll
        for (int r = 0; r < 2; ++r) {
            psum[r] += __shfl_xor_sync(0xffffffffu, psum[r], 1);
            psum[r] += __shfl_xor_sync(0xffffffffu, psum[r], 2);
            lrow[r] = lrow[r] * alpha[r] + psum[r];
        }
        #pragma unroll
        for (int ni = 0; ni < 8; ++ni)
            #pragma unroll
            for (int u = 0; u < 4; ++u)
                accO[ni][u] *= alpha[u >> 1];

        // ---- O += P V ----
        #pragma unroll
        for (int j = 0; j < 4; ++j) {
            uint32_t af[4];
            af[0] = pack2h(accS[2 * j][0],     accS[2 * j][1]);
            af[1] = pack2h(accS[2 * j][2],     accS[2 * j][3]);
            af[2] = pack2h(accS[2 * j + 1][0], accS[2 * j + 1][1]);
            af[3] = pack2h(accS[2 * j + 1][2], accS[2 * j + 1][3]);
            #pragma unroll
            for (int g = 0; g < 4; ++g) {
                uint32_t vf[4];
                uint32_t off = (uint32_t)((j * 16 + (lane & 15)) * FST + g * 16 + ((lane >> 4) << 3)) * 2;
                ldsm4t(vf, sV_b + off);
                mma16816(accO[2 * g],     af, vf);
                mma16816(accO[2 * g + 1], af, vf + 2);
            }
        }
        __syncthreads();
    }

    #pragma unroll
    for (int r = 0; r < 2; ++r) {
        float inv = 1.f / lrow[r];
        #pragma unroll
        for (int ni = 0; ni < 8; ++ni) {
            size_t o = (size_t)(b * LL + qr0 + 8 * r) * DD + h * DKH + ni * 8 + ec;
            *(uint32_t*)(ctxh + o) = pack2h(accO[ni][2 * r] * inv, accO[ni][2 * r + 1] * inv);
        }
    }
}

// ------------- LayerNorm ------------------------------------------------------
template<bool SPLIT>
__global__ void __launch_bounds__(256)
ln_kernel(const float* __restrict__ X, const float* __restrict__ g,
          const float* __restrict__ bt, float* __restrict__ O,
          fp16* __restrict__ Oh)
{
    const int row = blockIdx.x;
    const float* x = X + (size_t)row * DD;
    const int tid = threadIdx.x;

    float v[3];
    #pragma unroll
    for (int i = 0; i < 3; ++i) v[i] = x[tid + i * 256];

    __shared__ float red[256];
    float s = v[0] + v[1] + v[2];
    red[tid] = s; __syncthreads();
    for (int st = 128; st > 0; st >>= 1) {
        if (tid < st) red[tid] += red[tid + st];
        __syncthreads();
    }
    float mean = red[0] * (1.0f / DD);
    __syncthreads();

    float d0 = v[0] - mean, d1 = v[1] - mean, d2 = v[2] - mean;
    red[tid] = d0 * d0 + d1 * d1 + d2 * d2; __syncthreads();
    for (int st = 128; st > 0; st >>= 1) {
        if (tid < st) red[tid] += red[tid + st];
        __syncthreads();
    }
    float var = red[0] * (1.0f / DD);
    float inv = rsqrtf(var + 1e-5f);

    #pragma unroll
    for (int i = 0; i < 3; ++i) {
        int c = tid + i * 256;
        float o = (v[i] - mean) * inv * g[c] + bt[c];
        O[(size_t)row * DD + c] = o;
        if (SPLIT) Oh[(size_t)row * DD + c] = __float2half_rn(o);
    }
}

// ------------------------------- launch ---------------------------------------
extern "C" void kernel_launch(void* const* d_in, const int* in_sizes, int n_in,
                              void* d_out, int out_size)
{
    const float* tokens = (const float*)d_in[0];
    const float* pos    = (const float*)d_in[1];
    const float* pmask  = (const float*)d_in[2];
    const float* amask  = (const float*)d_in[3];
    const unsigned char* pad = (const unsigned char*)d_in[4];
    const float* Wq = (const float*)d_in[5];
    const float* bq = (const float*)d_in[6];
    const float* Wk = (const float*)d_in[7];
    const float* bk = (const float*)d_in[8];
    const float* Wv = (const float*)d_in[9];
    const float* bv = (const float*)d_in[10];
    const float* Wo = (const float*)d_in[11];
    const float* bo = (const float*)d_in[12];
    const float* table = (const float*)d_in[13];
    const float* W1 = (const float*)d_in[14];
    const float* b1 = (const float*)d_in[15];
    const float* W2 = (const float*)d_in[16];
    const float* b2 = (const float*)d_in[17];
    const float* ln1g = (const float*)d_in[18];
    const float* ln1b = (const float*)d_in[19];
    const float* ln2g = (const float*)d_in[20];
    const float* ln2b = (const float*)d_in[21];
    float* out = (float*)d_out;

    float *Pb, *Tb, *bqkv;
    cudaGetSymbolAddress((void**)&Pb, g_pre);
    cudaGetSymbolAddress((void**)&Tb, g_t1);
    cudaGetSymbolAddress((void**)&bqkv, g_bqkv);

    uint16_t* idxb;
    cudaGetSymbolAddress((void**)&idxb, g_idx);

    fp16 *tokh, *qkvh, *ctxh, *t1h, *ffh;
    cudaGetSymbolAddress((void**)&tokh, g_tokh);
    cudaGetSymbolAddress((void**)&qkvh, g_qkvh);
    cudaGetSymbolAddress((void**)&ctxh, g_ctxh);
    cudaGetSymbolAddress((void**)&t1h, g_t1h);
    cudaGetSymbolAddress((void**)&ffh, g_ffh);

    fp16 *wqkvh, *woh, *w1h, *w2h;
    cudaGetSymbolAddress((void**)&wqkvh, g_wqkvh);
    cudaGetSymbolAddress((void**)&woh, g_woh);
    cudaGetSymbolAddress((void**)&w1h, g_w1h);
    cudaGetSymbolAddress((void**)&w2h, g_w2h);

    // prep
    cvt_wT4<<<dim3(DD / 32, DD / 32, 4), 256>>>(Wq, Wk, Wv, Wo, wqkvh, woh);
    cvt_wT<<<dim3(FF / 32, DD / 32), 256>>>(W1, w1h, DD, FF);
    cvt_wT<<<dim3(DD / 32, FF / 32), 256>>>(W2, w2h, FF, DD);
    {
        int n4 = BL * DD / 4;
        int nblk = (n4 + QN + 255) / 256;
        cvt_split_bias<<<nblk, 256>>>(tokens, tokh, n4, bq, bk, bv, bqkv);
    }
    idx_kernel<<<(int)(((size_t)BB * LL * LL / 4 + 255) / 256), 256>>>(pos, amask, pad, idxb);

    // fused QKV GEMM -> fp16
    gemm_mma<3><<<dim3(QN / 128, BL / 128), 256>>>(tokh, wqkvh, bqkv,
                                                   nullptr, nullptr, qkvh, DD, QN);

    // fused attention -> ctx fp16
    dim3 gfa(LL / 64, BB * HH);
    flash_kernel<<<gfa, 128>>>(qkvh, pmask, idxb, table, ctxh);

    // out proj + residual -> fp32, LN1 (emits fp32 + fp16)
    gemm_mma<2><<<dim3(DD / 128, BL / 128), 256>>>(ctxh, woh, bo,
                                                   tokens, Pb, nullptr, DD, DD);
    ln_kernel<true><<<BL, 256>>>(Pb, ln1g, ln1b, Tb, t1h);

    // FFN
    gemm_mma<4><<<dim3(FF / 128, BL / 128), 256>>>(t1h, w1h, b1,
                                                   nullptr, nullptr, ffh, DD, FF);
    gemm_mma<2><<<dim3(DD / 128, BL / 128), 256>>>(ffh, w2h, b2,
                                                   Tb, Pb, nullptr, FF, DD);
    ln_kernel<false><<<BL, 256>>>(Pb, ln2g, ln2b, out, nullptr);
}